// round 12
// baseline (speedup 1.0000x reference)
#include <cuda_runtime.h>
#include <cuda_bf16.h>
#include <math.h>

// Problem constants
#define B_    32
#define HID_  4096
#define NH_   32
#define NKV_  8
#define HD_   128
#define BS_   16
#define MAXB_ 128
#define S_    2048
#define QKV_N 6144           // (NH + 2*NKV) * HD
#define NCHUNK 16            // flash-decode chunks of 128 keys
#define CHUNK 128
#define PART_STRIDE 528      // floats per attention partial record (16B aligned)

#define SPLITK 16            // GEMM split-K
#define GSLICE 256           // K rows per split slice (4096/16)
#define GNCH   16            // 16-row chunks per slice
#define WPAD   136           // padded smem row stride (floats)
#define GNT    128           // N cols per GEMM block (4 warps x n32)

// ------------------------- scratch (device globals) -------------------------
// Referenced ONLY inside device code (host-side symbol decay = round-0 bug).
__device__ __align__(16) float g_fragA_hi[B_ * HID_];         // tf32-hi A fragments
__device__ __align__(16) float g_fragA_lo[B_ * HID_];         // tf32-lo A fragments
__device__ __align__(16) float g_part[SPLITK * B_ * QKV_N];   // split-K partials
__device__ __align__(16) float g_qkv[B_ * QKV_N];             // roped qkv
__device__ __align__(16) float g_attn_part[B_ * NKV_ * NCHUNK * PART_STRIDE];
__device__ __align__(16) float g_attn_out[B_ * NH_ * HD_];

// ------------------------- helpers ------------------------------------------
__device__ __forceinline__ unsigned tf32u(float x) {
    unsigned r;
    asm("cvt.rna.tf32.f32 %0, %1;" : "=r"(r) : "f"(x));
    return r;
}

__device__ __forceinline__ void mma8(float acc[4], float4 a, unsigned b0, unsigned b1) {
    asm volatile(
        "mma.sync.aligned.m16n8k8.row.col.f32.tf32.tf32.f32 "
        "{%0,%1,%2,%3},{%4,%5,%6,%7},{%8,%9},{%0,%1,%2,%3};"
        : "+f"(acc[0]), "+f"(acc[1]), "+f"(acc[2]), "+f"(acc[3])
        : "r"(__float_as_uint(a.x)), "r"(__float_as_uint(a.y)),
          "r"(__float_as_uint(a.z)), "r"(__float_as_uint(a.w)),
          "r"(b0), "r"(b1));
}

// no-op: shifts the ncu capture window so launch #4 = gemm1
__global__ void noop_kernel() {}

// ------------------------- A-fragment prep (R4-verified layout) -------------
__global__ void __launch_bounds__(256) prep_frag_kernel(const float* __restrict__ A) {
    int idx = blockIdx.x * 256 + threadIdx.x;          // 131072 total
    int i    = idx & 3;
    int lane = (idx >> 2) & 31;
    int mt   = (idx >> 7) & 1;
    int k8   = idx >> 8;
    int row = mt * 16 + (lane >> 2) + (i & 1) * 8;
    int col = k8 * 8 + (lane & 3) + (i >> 1) * 4;
    float v = A[row * HID_ + col];
    float hi = __uint_as_float(tf32u(v));
    float lo = __uint_as_float(tf32u(v - hi));
    g_fragA_hi[idx] = hi;
    g_fragA_lo[idx] = lo;
}

__global__ void __launch_bounds__(256) prep_frag_attn_kernel() {
    int idx = blockIdx.x * 256 + threadIdx.x;
    int i    = idx & 3;
    int lane = (idx >> 2) & 31;
    int mt   = (idx >> 7) & 1;
    int k8   = idx >> 8;
    int row = mt * 16 + (lane >> 2) + (i & 1) * 8;
    int col = k8 * 8 + (lane & 3) + (i >> 1) * 4;
    float v = g_attn_out[row * (NH_ * HD_) + col];
    float hi = __uint_as_float(tf32u(v));
    float lo = __uint_as_float(tf32u(v - hi));
    g_fragA_hi[idx] = hi;
    g_fragA_lo[idx] = lo;
}

// ------------------------- 3xTF32 tensor-core GEMM --------------------------
// C[32,N] = A[32,4096] @ W[4096,N].  grid (N/GNT, SPLITK), block 128 (4 warps).
// Inner loop issues the 24 HMMAs per k8 as 3 passes of 8 INDEPENDENT
// accumulators (same-acc reuse distance 8) to cover HMMA latency.
__global__ void __launch_bounds__(128, 5) gemm_mma3_kernel(
    const float* __restrict__ W, int N)
{
    __shared__ float sW[4 * 16 * WPAD];   // 34.8 KB
    int tid = threadIdx.x;
    int w = tid >> 5, lane = tid & 31;
    int nb = blockIdx.x, kb = blockIdx.y;
    int n0 = nb * GNT;
    int k0 = kb * GSLICE;

    unsigned sbase;
    asm("{ .reg .u64 t; cvta.to.shared.u64 t, %1; cvt.u32.u64 %0, t; }"
        : "=r"(sbase) : "l"(sW));

#define STAGE(C) do { int _c = (C); int _buf = _c & 3;                        \
        const float* _src = W + (size_t)(k0 + _c * 16) * N + n0;              \
        unsigned _sb = sbase + (unsigned)(_buf * 16 * WPAD) * 4u;             \
        _Pragma("unroll")                                                     \
        for (int _p = 0; _p < 4; _p++) {                                      \
            int _f = _p * 128 + tid;                                          \
            int _row = _f >> 5, _c4 = _f & 31;                                \
            unsigned _dst = _sb + (unsigned)(_row * WPAD + _c4 * 4) * 4u;     \
            const float* _g = _src + (size_t)_row * N + _c4 * 4;              \
            asm volatile("cp.async.cg.shared.global [%0], [%1], 16;"          \
                         :: "r"(_dst), "l"(_g));                              \
        }                                                                     \
        asm volatile("cp.async.commit_group;"); } while (0)

    float acc[2][4][4];
#pragma unroll
    for (int mf = 0; mf < 2; mf++)
#pragma unroll
        for (int nf = 0; nf < 4; nf++)
#pragma unroll
            for (int i = 0; i < 4; i++) acc[mf][nf][i] = 0.f;

    const float4* fhi = (const float4*)g_fragA_hi;
    const float4* flo = (const float4*)g_fragA_lo;

    STAGE(0); STAGE(1); STAGE(2);

    for (int c = 0; c < GNCH; c++) {
        int rem = GNCH - 1 - c;
        if (rem >= 2)      asm volatile("cp.async.wait_group 2;" ::: "memory");
        else if (rem == 1) asm volatile("cp.async.wait_group 1;" ::: "memory");
        else               asm volatile("cp.async.wait_group 0;" ::: "memory");
        __syncthreads();
        if (c + 3 < GNCH) STAGE(c + 3);

        const float* sb0 = sW + (c & 3) * 16 * WPAD;
#pragma unroll
        for (int ko = 0; ko < 2; ko++) {
            int k8 = (k0 >> 3) + c * 2 + ko;
            float4 ah0 = __ldg(&fhi[(k8 * 2 + 0) * 32 + lane]);
            float4 ah1 = __ldg(&fhi[(k8 * 2 + 1) * 32 + lane]);
            float4 al0 = __ldg(&flo[(k8 * 2 + 0) * 32 + lane]);
            float4 al1 = __ldg(&flo[(k8 * 2 + 1) * 32 + lane]);
            const float* sb = sb0 + (ko * 8 + (lane & 3)) * WPAD + w * 32 + (lane >> 2);

            // gather + convert all 4 B fragment pairs first
            unsigned b0h[4], b1h[4], b0l[4], b1l[4];
#pragma unroll
            for (int nf = 0; nf < 4; nf++) {
                float b0 = sb[nf * 8];
                float b1 = sb[nf * 8 + 4 * WPAD];
                b0h[nf] = tf32u(b0); b1h[nf] = tf32u(b1);
                b0l[nf] = tf32u(b0 - __uint_as_float(b0h[nf]));
                b1l[nf] = tf32u(b1 - __uint_as_float(b1h[nf]));
            }
            // pass 1: hi x hi (8 independent accumulators)
#pragma unroll
            for (int nf = 0; nf < 4; nf++) mma8(acc[0][nf], ah0, b0h[nf], b1h[nf]);
#pragma unroll
            for (int nf = 0; nf < 4; nf++) mma8(acc[1][nf], ah1, b0h[nf], b1h[nf]);
            // pass 2: lo x hi
#pragma unroll
            for (int nf = 0; nf < 4; nf++) mma8(acc[0][nf], al0, b0h[nf], b1h[nf]);
#pragma unroll
            for (int nf = 0; nf < 4; nf++) mma8(acc[1][nf], al1, b0h[nf], b1h[nf]);
            // pass 3: hi x lo
#pragma unroll
            for (int nf = 0; nf < 4; nf++) mma8(acc[0][nf], ah0, b0l[nf], b1l[nf]);
#pragma unroll
            for (int nf = 0; nf < 4; nf++) mma8(acc[1][nf], ah1, b0l[nf], b1l[nf]);
        }
    }
#undef STAGE

    // writeback (R4-verified accumulator layout)
    float* op = g_part + (size_t)kb * 32 * N + n0 + w * 32;
    int r = lane >> 2, c2 = (lane & 3) * 2;
#pragma unroll
    for (int mf = 0; mf < 2; mf++)
#pragma unroll
        for (int nf = 0; nf < 4; nf++) {
            *(float2*)(op + (size_t)(mf * 16 + r    ) * N + nf * 8 + c2) =
                make_float2(acc[mf][nf][0], acc[mf][nf][1]);
            *(float2*)(op + (size_t)(mf * 16 + r + 8) * N + nf * 8 + c2) =
                make_float2(acc[mf][nf][2], acc[mf][nf][3]);
        }
}

// ------------------------- split-K sum + RoPE (q,k heads) -------------------
// grid: 320 = 32 b x 10 col-groups of 512. block 128.
__global__ void __launch_bounds__(128) rope_qk_kernel(const int* __restrict__ positions) {
    __shared__ float sq[512];
    __shared__ float scs[64], ssn[64];
    int blk = blockIdx.x;
    int grp = blk % 10;                 // 512-col group (4 heads)
    int b   = blk / 10;
    int tid = threadIdx.x;
    int pos = positions[b];
    int cbase = grp * 512;

    {
        int i4 = cbase / 4 + tid;
        float4 s = make_float4(0.f, 0.f, 0.f, 0.f);
#pragma unroll
        for (int j = 0; j < SPLITK; j++) {
            float4 t = ((const float4*)(g_part + (size_t)j * 32 * QKV_N + (size_t)b * QKV_N))[i4];
            s.x += t.x; s.y += t.y; s.z += t.z; s.w += t.w;
        }
        ((float4*)sq)[tid] = s;
    }
    if (tid < 64) {
        const double LOG_THETA_OVER_HALF = 0.20503692777194265;  // ln(500000)/64
        double inv = exp(-(double)tid * LOG_THETA_OVER_HALF);
        double f = (double)pos * inv;
        double sd, cd;
        sincos(f, &sd, &cd);
        scs[tid] = (float)cd; ssn[tid] = (float)sd;
    }
    __syncthreads();

    float* out = g_qkv + (size_t)b * QKV_N + cbase;
#pragma unroll
    for (int r = 0; r < 2; r++) {
        int p = tid + r * 128;
        int h = p >> 6, d = p & 63;
        int c1 = h * 128 + d, c2 = c1 + 64;
        float x1 = sq[c1], x2 = sq[c2];
        float cs = scs[d], sn = ssn[d];
        out[c1] = x1 * cs - x2 * sn;
        out[c2] = x2 * cs + x1 * sn;
    }
}

// ------------------------- split-K sum, v passthrough ------------------------
// grid: 64 = 32 b x 2 groups. block 128.
__global__ void __launch_bounds__(128) rope_v_kernel() {
    int blk = blockIdx.x;
    int grp = blk & 1;
    int b   = blk >> 1;
    int tid = threadIdx.x;
    int i4 = (5120 + grp * 512) / 4 + tid;
    float4 s = make_float4(0.f, 0.f, 0.f, 0.f);
#pragma unroll
    for (int j = 0; j < SPLITK; j++) {
        float4 t = ((const float4*)(g_part + (size_t)j * 32 * QKV_N + (size_t)b * QKV_N))[i4];
        s.x += t.x; s.y += t.y; s.z += t.z; s.w += t.w;
    }
    ((float4*)(g_qkv + (size_t)b * QKV_N))[i4] = s;
}

// ------------------------- attention partial (flash-decode) -----------------
// grid: B*NKV*NCHUNK = 4096, block 256 (8 warps, warp-per-key-pair).
__global__ void __launch_bounds__(256, 3) attn_partial_kernel(
    const float* __restrict__ kc, const float* __restrict__ vc,
    const int* __restrict__ positions, const int* __restrict__ bt)
{
    int x = blockIdx.x;
    int c  = x & (NCHUNK - 1);
    int kv = (x >> 4) & 7;
    int b  = x >> 7;
    int tid = threadIdx.x;
    int pos = positions[b];
    int L = pos + 1;
    int s0 = c * CHUNK;
    if (s0 >= L) return;                 // empty chunk: combine skips it
    int s1 = min(s0 + CHUNK, L);
    int sEnd = min(s1, pos);             // cache keys strictly below pos
    bool hasNew = (pos < s1);            // this chunk owns the new token

    float* pbase = g_attn_part + (size_t)x * PART_STRIDE;

    __shared__ int sbt[8];               // block-table slice for 128-key chunk
    if (tid < 8) sbt[tid] = bt[b * MAXB_ + (s0 >> 4) + tid];
    __syncthreads();

    int w = tid >> 5, lane = tid & 31;
    bool b1 = (lane & 1), b2 = (lane & 2), b4 = (lane & 4);
    const float4* qp = (const float4*)(g_qkv + (size_t)b * QKV_N + kv * 512);
    const float SCALE = 0.08838834764831845f;   // 1/sqrt(128)
    float4 q[4];
#pragma unroll
    for (int g = 0; g < 4; g++) {
        float4 t = qp[g * 32 + lane];
        q[g] = make_float4(t.x * SCALE, t.y * SCALE, t.z * SCALE, t.w * SCALE);
    }
    const float4* knew = (const float4*)(g_qkv + (size_t)b * QKV_N + 4096 + kv * 128);
    const float4* vnew = (const float4*)(g_qkv + (size_t)b * QKV_N + 5120 + kv * 128);

    const float* kcb = kc + (size_t)kv * 128 + lane * 4;
    const float* vcb = vc + (size_t)kv * 128 + lane * 4;

    float l1 = 0.f;
    float4 acc[4];
#pragma unroll
    for (int g = 0; g < 4; g++) acc[g] = make_float4(0.f, 0.f, 0.f, 0.f);

#define LOADQ(I, SX) do { int _s = (SX);                                   \
        if (_s < sEnd) {                                                   \
            int _slot = sbt[(_s - s0) >> 4] * 16 + (_s & 15);              \
            const float* _kp = kcb + ((size_t)_slot << 10);                \
            const float* _vp = vcb + ((size_t)_slot << 10);                \
            asm volatile("ld.global.cg.v4.f32 {%0,%1,%2,%3}, [%4];"        \
                : "=f"(kq[I].x), "=f"(kq[I].y), "=f"(kq[I].z), "=f"(kq[I].w) \
                : "l"(_kp));                                               \
            asm volatile("ld.global.cg.v4.f32 {%0,%1,%2,%3}, [%4];"        \
                : "=f"(vq[I].x), "=f"(vq[I].y), "=f"(vq[I].z), "=f"(vq[I].w) \
                : "l"(_vp));                                               \
        } } while (0)

#define STEP2(kkA, vvA, kkB, vvB, useB) do {                               \
        float a0 = fmaf(q[0].x, kkA.x, fmaf(q[0].y, kkA.y, fmaf(q[0].z, kkA.z, q[0].w * kkA.w))); \
        float a1 = fmaf(q[1].x, kkA.x, fmaf(q[1].y, kkA.y, fmaf(q[1].z, kkA.z, q[1].w * kkA.w))); \
        float a2 = fmaf(q[2].x, kkA.x, fmaf(q[2].y, kkA.y, fmaf(q[2].z, kkA.z, q[2].w * kkA.w))); \
        float a3 = fmaf(q[3].x, kkA.x, fmaf(q[3].y, kkA.y, fmaf(q[3].z, kkA.z, q[3].w * kkA.w))); \
        float c0 = fmaf(q[0].x, kkB.x, fmaf(q[0].y, kkB.y, fmaf(q[0].z, kkB.z, q[0].w * kkB.w))); \
        float c1 = fmaf(q[1].x, kkB.x, fmaf(q[1].y, kkB.y, fmaf(q[1].z, kkB.z, q[1].w * kkB.w))); \
        float c2 = fmaf(q[2].x, kkB.x, fmaf(q[2].y, kkB.y, fmaf(q[2].z, kkB.z, q[2].w * kkB.w))); \
        float c3 = fmaf(q[3].x, kkB.x, fmaf(q[3].y, kkB.y, fmaf(q[3].z, kkB.z, q[3].w * kkB.w))); \
        float vA01 = (b1 ? a1 : a0) + __shfl_xor_sync(0xffffffffu, b1 ? a0 : a1, 1); \
        float vA23 = (b1 ? a3 : a2) + __shfl_xor_sync(0xffffffffu, b1 ? a2 : a3, 1); \
        float vB01 = (b1 ? c1 : c0) + __shfl_xor_sync(0xffffffffu, b1 ? c0 : c1, 1); \
        float vB23 = (b1 ? c3 : c2) + __shfl_xor_sync(0xffffffffu, b1 ? c2 : c3, 1); \
        float vA = (b2 ? vA23 : vA01) + __shfl_xor_sync(0xffffffffu, b2 ? vA01 : vA23, 2); \
        float vB = (b2 ? vB23 : vB01) + __shfl_xor_sync(0xffffffffu, b2 ? vB01 : vB23, 2); \
        float vv_ = (b4 ? vB : vA) + __shfl_xor_sync(0xffffffffu, b4 ? vA : vB, 4); \
        vv_ += __shfl_xor_sync(0xffffffffu, vv_, 8);                       \
        vv_ += __shfl_xor_sync(0xffffffffu, vv_, 16);                      \
        float px = __expf(vv_);                                            \
        if (b4 && !(useB)) px = 0.f;                                       \
        l1 += px;                                                          \
        float pA0 = __shfl_sync(0xffffffffu, px, 0, 8);                    \
        float pA1 = __shfl_sync(0xffffffffu, px, 1, 8);                    \
        float pA2 = __shfl_sync(0xffffffffu, px, 2, 8);                    \
        float pA3 = __shfl_sync(0xffffffffu, px, 3, 8);                    \
        float pB0 = __shfl_sync(0xffffffffu, px, 4, 8);                    \
        float pB1 = __shfl_sync(0xffffffffu, px, 5, 8);                    \
        float pB2 = __shfl_sync(0xffffffffu, px, 6, 8);                    \
        float pB3 = __shfl_sync(0xffffffffu, px, 7, 8);                    \
        acc[0].x = fmaf(pA0, vvA.x, fmaf(pB0, vvB.x, acc[0].x));           \
        acc[0].y = fmaf(pA0, vvA.y, fmaf(pB0, vvB.y, acc[0].y));           \
        acc[0].z = fmaf(pA0, vvA.z, fmaf(pB0, vvB.z, acc[0].z));           \
        acc[0].w = fmaf(pA0, vvA.w, fmaf(pB0, vvB.w, acc[0].w));           \
        acc[1].x = fmaf(pA1, vvA.x, fmaf(pB1, vvB.x, acc[1].x));           \
        acc[1].y = fmaf(pA1, vvA.y, fmaf(pB1, vvB.y, acc[1].y));           \
        acc[1].z = fmaf(pA1, vvA.z, fmaf(pB1, vvB.z, acc[1].z));           \
        acc[1].w = fmaf(pA1, vvA.w, fmaf(pB1, vvB.w, acc[1].w));           \
        acc[2].x = fmaf(pA2, vvA.x, fmaf(pB2, vvB.x, acc[2].x));           \
        acc[2].y = fmaf(pA2, vvA.y, fmaf(pB2, vvB.y, acc[2].y));           \
        acc[2].z = fmaf(pA2, vvA.z, fmaf(pB2, vvB.z, acc[2].z));           \
        acc[2].w = fmaf(pA2, vvA.w, fmaf(pB2, vvB.w, acc[2].w));           \
        acc[3].x = fmaf(pA3, vvA.x, fmaf(pB3, vvB.x, acc[3].x));           \
        acc[3].y = fmaf(pA3, vvA.y, fmaf(pB3, vvB.y, acc[3].y));           \
        acc[3].z = fmaf(pA3, vvA.z, fmaf(pB3, vvB.z, acc[3].z));           \
        acc[3].w = fmaf(pA3, vvA.w, fmaf(pB3, vvB.w, acc[3].w));           \
    } while (0)

    float4 kq[2], vq[2];
#pragma unroll
    for (int i = 0; i < 2; i++) { kq[i] = make_float4(0,0,0,0); vq[i] = kq[i]; }
    int s = s0 + w;
    LOADQ(0, s); LOADQ(1, s + 8);

    for (; s < sEnd; s += 16) {
        float4 kkA = kq[0], vvA = vq[0], kkB = kq[1], vvB = vq[1];
        bool useB = (s + 8 < sEnd);      // warp-uniform
        LOADQ(0, s + 16); LOADQ(1, s + 24);
        STEP2(kkA, vvA, kkB, vvB, useB);
    }

    if (hasNew && w == 0) {
        float4 kk = knew[lane], vv = vnew[lane];
        float4 zz = make_float4(0.f, 0.f, 0.f, 0.f);
        STEP2(kk, vv, zz, zz, false);
    }
#undef LOADQ
#undef STEP2

    l1 += __shfl_xor_sync(0xffffffffu, l1, 4);

    __shared__ float sm_l[8][4];
    __shared__ float4 sm_acc[8][4][32];
    if (lane < 4) sm_l[w][lane] = l1;
#pragma unroll
    for (int g = 0; g < 4; g++) sm_acc[w][g][lane] = acc[g];
    __syncthreads();

    if (tid < 128) {
        int g = tid >> 5;
        int ln = tid & 31;
        float ll = 0.f;
        float4 aa = make_float4(0.f, 0.f, 0.f, 0.f);
#pragma unroll
        for (int ww = 0; ww < 8; ww++) {
            ll += sm_l[ww][g];
            float4 t = sm_acc[ww][g][ln];
            aa.x += t.x; aa.y += t.y; aa.z += t.z; aa.w += t.w;
        }
        if (ln == 0) pbase[4 + g] = ll;
        ((float4*)(pbase + 8))[g * 32 + ln] = aa;
    }
}

// ------------------------- attention combine --------------------------------
// grid: B*NKV = 256, block 128. Plain sum of active chunks (fixed reference).
__global__ void __launch_bounds__(128) attn_combine_kernel(const int* __restrict__ positions) {
    int x = blockIdx.x;                 // b*8 + kv
    int b = x >> 3;
    int L = positions[b] + 1;
    int nc = min(NCHUNK, (L + CHUNK - 1) / CHUNK);
    int g = threadIdx.x >> 5;
    int ln = threadIdx.x & 31;
    const float* base0 = g_attn_part + (size_t)x * NCHUNK * PART_STRIDE;

    float ll = 0.f;
    float4 aa = make_float4(0.f, 0.f, 0.f, 0.f);
#pragma unroll
    for (int hw = 0; hw < 2; hw++) {
        float lv[8];
        float4 tv[8];
#pragma unroll
        for (int j = 0; j < 8; j++) {
            int c = hw * 8 + j;
            const float* base = base0 + (size_t)c * PART_STRIDE;
            if (c < nc) {
                lv[j] = base[4 + g];
                tv[j] = ((const float4*)(base + 8))[g * 32 + ln];
            } else {
                lv[j] = 0.f; tv[j] = make_float4(0.f, 0.f, 0.f, 0.f);
            }
        }
#pragma unroll
        for (int j = 0; j < 8; j++) {
            ll += lv[j];
            aa.x += tv[j].x; aa.y += tv[j].y; aa.z += tv[j].z; aa.w += tv[j].w;
        }
    }
    float inv = 1.f / ll;
    ((float4*)g_attn_out)[(size_t)x * 128 + g * 32 + ln] =
        make_float4(aa.x * inv, aa.y * inv, aa.z * inv, aa.w * inv);
}

// ------------------------- final split-K reduce ------------------------------
__global__ void __launch_bounds__(256) add_out_kernel(float* __restrict__ out) {
    int i = blockIdx.x * 256 + threadIdx.x;       // float4 index, 32768 total
    float4 s = make_float4(0.f, 0.f, 0.f, 0.f);
#pragma unroll
    for (int j = 0; j < SPLITK; j++) {
        float4 t = ((const float4*)g_part)[(size_t)j * (B_ * HID_ / 4) + i];
        s.x += t.x; s.y += t.y; s.z += t.z; s.w += t.w;
    }
    ((float4*)out)[i] = s;
}

// ------------------------- launch ------------------------------------------
extern "C" void kernel_launch(void* const* d_in, const int* in_sizes, int n_in,
                              void* d_out, int out_size) {
    const float* hidden = 0; const float* w_qkv = 0; const float* w_o = 0;
    const float* k_cache = 0; const float* v_cache = 0;
    const int* positions = 0; const int* btables = 0;
    for (int i = 0; i < n_in; i++) {
        int sz = in_sizes[i];
        if (sz == B_ * HID_)               hidden  = (const float*)d_in[i];
        else if (sz == HID_ * QKV_N)       w_qkv   = (const float*)d_in[i];
        else if (sz == NH_ * HD_ * HID_)   w_o     = (const float*)d_in[i];
        else if (sz == 4096 * BS_ * NKV_ * HD_) {
            if (!k_cache) k_cache = (const float*)d_in[i];
            else if (!v_cache) v_cache = (const float*)d_in[i];
        }
        else if (sz == B_) { if (!positions) positions = (const int*)d_in[i]; }
        else if (sz == B_ * MAXB_)         btables = (const int*)d_in[i];
    }
    float* out = (float*)d_out;

    // two no-ops so the ncu capture window (launch #4) lands on gemm1
    noop_kernel<<<1, 32>>>();
    noop_kernel<<<1, 32>>>();
    // 1. qkv = hidden @ w_qkv  (3xTF32 mma, split-K=16, cp.async W pipeline)
    prep_frag_kernel<<<512, 256>>>(hidden);
    gemm_mma3_kernel<<<dim3(QKV_N / GNT, SPLITK), 128>>>(w_qkv, QKV_N);
    // 2. combine + RoPE
    rope_qk_kernel<<<B_ * 10, 128>>>(positions);
    rope_v_kernel<<<B_ * 2, 128>>>();
    // 3. paged attention (flash-decode partials + combine)
    attn_partial_kernel<<<B_ * NKV_ * NCHUNK, 256>>>(k_cache, v_cache, positions, btables);
    attn_combine_kernel<<<B_ * NKV_, 128>>>(positions);
    // 4. out = attn @ w_o
    prep_frag_attn_kernel<<<512, 256>>>();
    gemm_mma3_kernel<<<dim3(HID_ / GNT, SPLITK), 128>>>(w_o, HID_);
    add_out_kernel<<<B_ * HID_ / 4 / 256, 256>>>(out);
}

// round 13
// speedup vs baseline: 1.0002x; 1.0002x over previous
#include <cuda_runtime.h>
#include <cuda_bf16.h>
#include <math.h>

// Problem constants
#define B_    32
#define HID_  4096
#define NH_   32
#define NKV_  8
#define HD_   128
#define BS_   16
#define MAXB_ 128
#define S_    2048
#define QKV_N 6144           // (NH + 2*NKV) * HD
#define NCHUNK 16            // flash-decode chunks of 128 keys
#define CHUNK 128
#define PART_STRIDE 528      // floats per attention partial record (16B aligned)

#define SPLITK 16            // GEMM split-K
#define GSLICE 256           // K rows per split slice (4096/16)
#define GNCH   16            // 16-row chunks per slice
#define WPAD   136           // padded smem row stride (floats)
#define GNT    128           // N cols per GEMM block (4 warps x n32)

// ------------------------- scratch (device globals) -------------------------
// Referenced ONLY inside device code (host-side symbol decay = round-0 bug).
__device__ __align__(16) float g_fragA_hi[B_ * HID_];         // tf32-hi A fragments
__device__ __align__(16) float g_fragA_lo[B_ * HID_];         // tf32-lo A fragments
__device__ __align__(16) float g_part[SPLITK * B_ * QKV_N];   // split-K partials
__device__ __align__(16) float g_qkv[B_ * QKV_N];             // roped qkv
__device__ __align__(16) float g_attn_part[B_ * NKV_ * NCHUNK * PART_STRIDE];
__device__ __align__(16) float g_attn_out[B_ * NH_ * HD_];

// ------------------------- helpers ------------------------------------------
__device__ __forceinline__ unsigned tf32u(float x) {
    unsigned r;
    asm("cvt.rna.tf32.f32 %0, %1;" : "=r"(r) : "f"(x));
    return r;
}

__device__ __forceinline__ void mma8(float acc[4], float4 a, unsigned b0, unsigned b1) {
    asm volatile(
        "mma.sync.aligned.m16n8k8.row.col.f32.tf32.tf32.f32 "
        "{%0,%1,%2,%3},{%4,%5,%6,%7},{%8,%9},{%0,%1,%2,%3};"
        : "+f"(acc[0]), "+f"(acc[1]), "+f"(acc[2]), "+f"(acc[3])
        : "r"(__float_as_uint(a.x)), "r"(__float_as_uint(a.y)),
          "r"(__float_as_uint(a.z)), "r"(__float_as_uint(a.w)),
          "r"(b0), "r"(b1));
}

// no-op: shifts the ncu capture window so launch #4 = gemm1
__global__ void noop_kernel() {}

// ------------------------- A-fragment prep (R4-verified layout) -------------
__global__ void __launch_bounds__(256) prep_frag_kernel(const float* __restrict__ A) {
    int idx = blockIdx.x * 256 + threadIdx.x;          // 131072 total
    int i    = idx & 3;
    int lane = (idx >> 2) & 31;
    int mt   = (idx >> 7) & 1;
    int k8   = idx >> 8;
    int row = mt * 16 + (lane >> 2) + (i & 1) * 8;
    int col = k8 * 8 + (lane & 3) + (i >> 1) * 4;
    float v = A[row * HID_ + col];
    float hi = __uint_as_float(tf32u(v));
    float lo = __uint_as_float(tf32u(v - hi));
    g_fragA_hi[idx] = hi;
    g_fragA_lo[idx] = lo;
}

__global__ void __launch_bounds__(256) prep_frag_attn_kernel() {
    int idx = blockIdx.x * 256 + threadIdx.x;
    int i    = idx & 3;
    int lane = (idx >> 2) & 31;
    int mt   = (idx >> 7) & 1;
    int k8   = idx >> 8;
    int row = mt * 16 + (lane >> 2) + (i & 1) * 8;
    int col = k8 * 8 + (lane & 3) + (i >> 1) * 4;
    float v = g_attn_out[row * (NH_ * HD_) + col];
    float hi = __uint_as_float(tf32u(v));
    float lo = __uint_as_float(tf32u(v - hi));
    g_fragA_hi[idx] = hi;
    g_fragA_lo[idx] = lo;
}

// ------------------------- 3xTF32 tensor-core GEMM --------------------------
// C[32,N] = A[32,4096] @ W[4096,N].  grid (N/GNT, SPLITK), block 128 (4 warps).
// Flat k8 loop with A-fragment REGISTER PREFETCH one k8 ahead (crosses chunk
// barriers) so HMMAs never wait on the ~250cyc L2 fragment loads.
__global__ void __launch_bounds__(128, 4) gemm_mma3_kernel(
    const float* __restrict__ W, int N)
{
    __shared__ float sW[4 * 16 * WPAD];   // 34.8 KB
    int tid = threadIdx.x;
    int w = tid >> 5, lane = tid & 31;
    int nb = blockIdx.x, kb = blockIdx.y;
    int n0 = nb * GNT;
    int k0 = kb * GSLICE;
    int k8base = k0 >> 3;

    unsigned sbase;
    asm("{ .reg .u64 t; cvta.to.shared.u64 t, %1; cvt.u32.u64 %0, t; }"
        : "=r"(sbase) : "l"(sW));

#define STAGE(C) do { int _c = (C); int _buf = _c & 3;                        \
        const float* _src = W + (size_t)(k0 + _c * 16) * N + n0;              \
        unsigned _sb = sbase + (unsigned)(_buf * 16 * WPAD) * 4u;             \
        _Pragma("unroll")                                                     \
        for (int _p = 0; _p < 4; _p++) {                                      \
            int _f = _p * 128 + tid;                                          \
            int _row = _f >> 5, _c4 = _f & 31;                                \
            unsigned _dst = _sb + (unsigned)(_row * WPAD + _c4 * 4) * 4u;     \
            const float* _g = _src + (size_t)_row * N + _c4 * 4;              \
            asm volatile("cp.async.cg.shared.global [%0], [%1], 16;"          \
                         :: "r"(_dst), "l"(_g));                              \
        }                                                                     \
        asm volatile("cp.async.commit_group;"); } while (0)

    float acc[2][4][4];
#pragma unroll
    for (int mf = 0; mf < 2; mf++)
#pragma unroll
        for (int nf = 0; nf < 4; nf++)
#pragma unroll
            for (int i = 0; i < 4; i++) acc[mf][nf][i] = 0.f;

    const float4* fhi = (const float4*)g_fragA_hi;
    const float4* flo = (const float4*)g_fragA_lo;

    // prefetch k8 #0 fragments
    float4 nah0 = __ldg(&fhi[(size_t)(k8base * 2 + 0) * 32 + lane]);
    float4 nah1 = __ldg(&fhi[(size_t)(k8base * 2 + 1) * 32 + lane]);
    float4 nal0 = __ldg(&flo[(size_t)(k8base * 2 + 0) * 32 + lane]);
    float4 nal1 = __ldg(&flo[(size_t)(k8base * 2 + 1) * 32 + lane]);

    STAGE(0); STAGE(1); STAGE(2);

    for (int kk = 0; kk < 32; kk++) {
        if ((kk & 1) == 0) {                        // chunk boundary
            int c = kk >> 1;
            int rem = GNCH - 1 - c;
            if (rem >= 2)      asm volatile("cp.async.wait_group 2;" ::: "memory");
            else if (rem == 1) asm volatile("cp.async.wait_group 1;" ::: "memory");
            else               asm volatile("cp.async.wait_group 0;" ::: "memory");
            __syncthreads();
            if (c + 3 < GNCH) STAGE(c + 3);
        }

        // rotate prefetched A fragments; issue next k8's loads immediately
        float4 ah0 = nah0, ah1 = nah1, al0 = nal0, al1 = nal1;
        if (kk < 31) {
            int k8n = k8base + kk + 1;
            nah0 = __ldg(&fhi[(size_t)(k8n * 2 + 0) * 32 + lane]);
            nah1 = __ldg(&fhi[(size_t)(k8n * 2 + 1) * 32 + lane]);
            nal0 = __ldg(&flo[(size_t)(k8n * 2 + 0) * 32 + lane]);
            nal1 = __ldg(&flo[(size_t)(k8n * 2 + 1) * 32 + lane]);
        }

        const float* sb = sW + ((kk >> 1) & 3) * 16 * WPAD
                        + ((kk & 1) * 8 + (lane & 3)) * WPAD + w * 32 + (lane >> 2);

        // gather + convert all 4 B fragment pairs
        unsigned b0h[4], b1h[4], b0l[4], b1l[4];
#pragma unroll
        for (int nf = 0; nf < 4; nf++) {
            float b0 = sb[nf * 8];
            float b1 = sb[nf * 8 + 4 * WPAD];
            b0h[nf] = tf32u(b0); b1h[nf] = tf32u(b1);
            b0l[nf] = tf32u(b0 - __uint_as_float(b0h[nf]));
            b1l[nf] = tf32u(b1 - __uint_as_float(b1h[nf]));
        }
        // 3 passes of 8 independent accumulators
#pragma unroll
        for (int nf = 0; nf < 4; nf++) mma8(acc[0][nf], ah0, b0h[nf], b1h[nf]);
#pragma unroll
        for (int nf = 0; nf < 4; nf++) mma8(acc[1][nf], ah1, b0h[nf], b1h[nf]);
#pragma unroll
        for (int nf = 0; nf < 4; nf++) mma8(acc[0][nf], al0, b0h[nf], b1h[nf]);
#pragma unroll
        for (int nf = 0; nf < 4; nf++) mma8(acc[1][nf], al1, b0h[nf], b1h[nf]);
#pragma unroll
        for (int nf = 0; nf < 4; nf++) mma8(acc[0][nf], ah0, b0l[nf], b1l[nf]);
#pragma unroll
        for (int nf = 0; nf < 4; nf++) mma8(acc[1][nf], ah1, b0l[nf], b1l[nf]);
    }
#undef STAGE

    // writeback (R4-verified accumulator layout)
    float* op = g_part + (size_t)kb * 32 * N + n0 + w * 32;
    int r = lane >> 2, c2 = (lane & 3) * 2;
#pragma unroll
    for (int mf = 0; mf < 2; mf++)
#pragma unroll
        for (int nf = 0; nf < 4; nf++) {
            *(float2*)(op + (size_t)(mf * 16 + r    ) * N + nf * 8 + c2) =
                make_float2(acc[mf][nf][0], acc[mf][nf][1]);
            *(float2*)(op + (size_t)(mf * 16 + r + 8) * N + nf * 8 + c2) =
                make_float2(acc[mf][nf][2], acc[mf][nf][3]);
        }
}

// ------------------------- split-K sum + RoPE (q,k heads) -------------------
// grid: 320 = 32 b x 10 col-groups of 512. block 128.
__global__ void __launch_bounds__(128) rope_qk_kernel(const int* __restrict__ positions) {
    __shared__ float sq[512];
    __shared__ float scs[64], ssn[64];
    int blk = blockIdx.x;
    int grp = blk % 10;                 // 512-col group (4 heads)
    int b   = blk / 10;
    int tid = threadIdx.x;
    int pos = positions[b];
    int cbase = grp * 512;

    {
        int i4 = cbase / 4 + tid;
        float4 s = make_float4(0.f, 0.f, 0.f, 0.f);
#pragma unroll
        for (int j = 0; j < SPLITK; j++) {
            float4 t = ((const float4*)(g_part + (size_t)j * 32 * QKV_N + (size_t)b * QKV_N))[i4];
            s.x += t.x; s.y += t.y; s.z += t.z; s.w += t.w;
        }
        ((float4*)sq)[tid] = s;
    }
    if (tid < 64) {
        const double LOG_THETA_OVER_HALF = 0.20503692777194265;  // ln(500000)/64
        double inv = exp(-(double)tid * LOG_THETA_OVER_HALF);
        double f = (double)pos * inv;
        double sd, cd;
        sincos(f, &sd, &cd);
        scs[tid] = (float)cd; ssn[tid] = (float)sd;
    }
    __syncthreads();

    float* out = g_qkv + (size_t)b * QKV_N + cbase;
#pragma unroll
    for (int r = 0; r < 2; r++) {
        int p = tid + r * 128;
        int h = p >> 6, d = p & 63;
        int c1 = h * 128 + d, c2 = c1 + 64;
        float x1 = sq[c1], x2 = sq[c2];
        float cs = scs[d], sn = ssn[d];
        out[c1] = x1 * cs - x2 * sn;
        out[c2] = x2 * cs + x1 * sn;
    }
}

// ------------------------- split-K sum, v passthrough ------------------------
// grid: 64 = 32 b x 2 groups. block 128.
__global__ void __launch_bounds__(128) rope_v_kernel() {
    int blk = blockIdx.x;
    int grp = blk & 1;
    int b   = blk >> 1;
    int tid = threadIdx.x;
    int i4 = (5120 + grp * 512) / 4 + tid;
    float4 s = make_float4(0.f, 0.f, 0.f, 0.f);
#pragma unroll
    for (int j = 0; j < SPLITK; j++) {
        float4 t = ((const float4*)(g_part + (size_t)j * 32 * QKV_N + (size_t)b * QKV_N))[i4];
        s.x += t.x; s.y += t.y; s.z += t.z; s.w += t.w;
    }
    ((float4*)(g_qkv + (size_t)b * QKV_N))[i4] = s;
}

// ------------------------- attention partial (flash-decode) -----------------
// grid: B*NKV*NCHUNK = 4096, block 256 (8 warps, warp-per-key-pair).
__global__ void __launch_bounds__(256, 3) attn_partial_kernel(
    const float* __restrict__ kc, const float* __restrict__ vc,
    const int* __restrict__ positions, const int* __restrict__ bt)
{
    int x = blockIdx.x;
    int c  = x & (NCHUNK - 1);
    int kv = (x >> 4) & 7;
    int b  = x >> 7;
    int tid = threadIdx.x;
    int pos = positions[b];
    int L = pos + 1;
    int s0 = c * CHUNK;
    if (s0 >= L) return;                 // empty chunk: combine skips it
    int s1 = min(s0 + CHUNK, L);
    int sEnd = min(s1, pos);             // cache keys strictly below pos
    bool hasNew = (pos < s1);            // this chunk owns the new token

    float* pbase = g_attn_part + (size_t)x * PART_STRIDE;

    __shared__ int sbt[8];               // block-table slice for 128-key chunk
    if (tid < 8) sbt[tid] = bt[b * MAXB_ + (s0 >> 4) + tid];
    __syncthreads();

    int w = tid >> 5, lane = tid & 31;
    bool b1 = (lane & 1), b2 = (lane & 2), b4 = (lane & 4);
    const float4* qp = (const float4*)(g_qkv + (size_t)b * QKV_N + kv * 512);
    const float SCALE = 0.08838834764831845f;   // 1/sqrt(128)
    float4 q[4];
#pragma unroll
    for (int g = 0; g < 4; g++) {
        float4 t = qp[g * 32 + lane];
        q[g] = make_float4(t.x * SCALE, t.y * SCALE, t.z * SCALE, t.w * SCALE);
    }
    const float4* knew = (const float4*)(g_qkv + (size_t)b * QKV_N + 4096 + kv * 128);
    const float4* vnew = (const float4*)(g_qkv + (size_t)b * QKV_N + 5120 + kv * 128);

    const float* kcb = kc + (size_t)kv * 128 + lane * 4;
    const float* vcb = vc + (size_t)kv * 128 + lane * 4;

    float l1 = 0.f;
    float4 acc[4];
#pragma unroll
    for (int g = 0; g < 4; g++) acc[g] = make_float4(0.f, 0.f, 0.f, 0.f);

#define LOADQ(I, SX) do { int _s = (SX);                                   \
        if (_s < sEnd) {                                                   \
            int _slot = sbt[(_s - s0) >> 4] * 16 + (_s & 15);              \
            const float* _kp = kcb + ((size_t)_slot << 10);                \
            const float* _vp = vcb + ((size_t)_slot << 10);                \
            asm volatile("ld.global.cg.v4.f32 {%0,%1,%2,%3}, [%4];"        \
                : "=f"(kq[I].x), "=f"(kq[I].y), "=f"(kq[I].z), "=f"(kq[I].w) \
                : "l"(_kp));                                               \
            asm volatile("ld.global.cg.v4.f32 {%0,%1,%2,%3}, [%4];"        \
                : "=f"(vq[I].x), "=f"(vq[I].y), "=f"(vq[I].z), "=f"(vq[I].w) \
                : "l"(_vp));                                               \
        } } while (0)

#define STEP2(kkA, vvA, kkB, vvB, useB) do {                               \
        float a0 = fmaf(q[0].x, kkA.x, fmaf(q[0].y, kkA.y, fmaf(q[0].z, kkA.z, q[0].w * kkA.w))); \
        float a1 = fmaf(q[1].x, kkA.x, fmaf(q[1].y, kkA.y, fmaf(q[1].z, kkA.z, q[1].w * kkA.w))); \
        float a2 = fmaf(q[2].x, kkA.x, fmaf(q[2].y, kkA.y, fmaf(q[2].z, kkA.z, q[2].w * kkA.w))); \
        float a3 = fmaf(q[3].x, kkA.x, fmaf(q[3].y, kkA.y, fmaf(q[3].z, kkA.z, q[3].w * kkA.w))); \
        float c0 = fmaf(q[0].x, kkB.x, fmaf(q[0].y, kkB.y, fmaf(q[0].z, kkB.z, q[0].w * kkB.w))); \
        float c1 = fmaf(q[1].x, kkB.x, fmaf(q[1].y, kkB.y, fmaf(q[1].z, kkB.z, q[1].w * kkB.w))); \
        float c2 = fmaf(q[2].x, kkB.x, fmaf(q[2].y, kkB.y, fmaf(q[2].z, kkB.z, q[2].w * kkB.w))); \
        float c3 = fmaf(q[3].x, kkB.x, fmaf(q[3].y, kkB.y, fmaf(q[3].z, kkB.z, q[3].w * kkB.w))); \
        float vA01 = (b1 ? a1 : a0) + __shfl_xor_sync(0xffffffffu, b1 ? a0 : a1, 1); \
        float vA23 = (b1 ? a3 : a2) + __shfl_xor_sync(0xffffffffu, b1 ? a2 : a3, 1); \
        float vB01 = (b1 ? c1 : c0) + __shfl_xor_sync(0xffffffffu, b1 ? c0 : c1, 1); \
        float vB23 = (b1 ? c3 : c2) + __shfl_xor_sync(0xffffffffu, b1 ? c2 : c3, 1); \
        float vA = (b2 ? vA23 : vA01) + __shfl_xor_sync(0xffffffffu, b2 ? vA01 : vA23, 2); \
        float vB = (b2 ? vB23 : vB01) + __shfl_xor_sync(0xffffffffu, b2 ? vB01 : vB23, 2); \
        float vv_ = (b4 ? vB : vA) + __shfl_xor_sync(0xffffffffu, b4 ? vA : vB, 4); \
        vv_ += __shfl_xor_sync(0xffffffffu, vv_, 8);                       \
        vv_ += __shfl_xor_sync(0xffffffffu, vv_, 16);                      \
        float px = __expf(vv_);                                            \
        if (b4 && !(useB)) px = 0.f;                                       \
        l1 += px;                                                          \
        float pA0 = __shfl_sync(0xffffffffu, px, 0, 8);                    \
        float pA1 = __shfl_sync(0xffffffffu, px, 1, 8);                    \
        float pA2 = __shfl_sync(0xffffffffu, px, 2, 8);                    \
        float pA3 = __shfl_sync(0xffffffffu, px, 3, 8);                    \
        float pB0 = __shfl_sync(0xffffffffu, px, 4, 8);                    \
        float pB1 = __shfl_sync(0xffffffffu, px, 5, 8);                    \
        float pB2 = __shfl_sync(0xffffffffu, px, 6, 8);                    \
        float pB3 = __shfl_sync(0xffffffffu, px, 7, 8);                    \
        acc[0].x = fmaf(pA0, vvA.x, fmaf(pB0, vvB.x, acc[0].x));           \
        acc[0].y = fmaf(pA0, vvA.y, fmaf(pB0, vvB.y, acc[0].y));           \
        acc[0].z = fmaf(pA0, vvA.z, fmaf(pB0, vvB.z, acc[0].z));           \
        acc[0].w = fmaf(pA0, vvA.w, fmaf(pB0, vvB.w, acc[0].w));           \
        acc[1].x = fmaf(pA1, vvA.x, fmaf(pB1, vvB.x, acc[1].x));           \
        acc[1].y = fmaf(pA1, vvA.y, fmaf(pB1, vvB.y, acc[1].y));           \
        acc[1].z = fmaf(pA1, vvA.z, fmaf(pB1, vvB.z, acc[1].z));           \
        acc[1].w = fmaf(pA1, vvA.w, fmaf(pB1, vvB.w, acc[1].w));           \
        acc[2].x = fmaf(pA2, vvA.x, fmaf(pB2, vvB.x, acc[2].x));           \
        acc[2].y = fmaf(pA2, vvA.y, fmaf(pB2, vvB.y, acc[2].y));           \
        acc[2].z = fmaf(pA2, vvA.z, fmaf(pB2, vvB.z, acc[2].z));           \
        acc[2].w = fmaf(pA2, vvA.w, fmaf(pB2, vvB.w, acc[2].w));           \
        acc[3].x = fmaf(pA3, vvA.x, fmaf(pB3, vvB.x, acc[3].x));           \
        acc[3].y = fmaf(pA3, vvA.y, fmaf(pB3, vvB.y, acc[3].y));           \
        acc[3].z = fmaf(pA3, vvA.z, fmaf(pB3, vvB.z, acc[3].z));           \
        acc[3].w = fmaf(pA3, vvA.w, fmaf(pB3, vvB.w, acc[3].w));           \
    } while (0)

    float4 kq[2], vq[2];
#pragma unroll
    for (int i = 0; i < 2; i++) { kq[i] = make_float4(0,0,0,0); vq[i] = kq[i]; }
    int s = s0 + w;
    LOADQ(0, s); LOADQ(1, s + 8);

    for (; s < sEnd; s += 16) {
        float4 kkA = kq[0], vvA = vq[0], kkB = kq[1], vvB = vq[1];
        bool useB = (s + 8 < sEnd);      // warp-uniform
        LOADQ(0, s + 16); LOADQ(1, s + 24);
        STEP2(kkA, vvA, kkB, vvB, useB);
    }

    if (hasNew && w == 0) {
        float4 kk = knew[lane], vv = vnew[lane];
        float4 zz = make_float4(0.f, 0.f, 0.f, 0.f);
        STEP2(kk, vv, zz, zz, false);
    }
#undef LOADQ
#undef STEP2

    l1 += __shfl_xor_sync(0xffffffffu, l1, 4);

    __shared__ float sm_l[8][4];
    __shared__ float4 sm_acc[8][4][32];
    if (lane < 4) sm_l[w][lane] = l1;
#pragma unroll
    for (int g = 0; g < 4; g++) sm_acc[w][g][lane] = acc[g];
    __syncthreads();

    if (tid < 128) {
        int g = tid >> 5;
        int ln = tid & 31;
        float ll = 0.f;
        float4 aa = make_float4(0.f, 0.f, 0.f, 0.f);
#pragma unroll
        for (int ww = 0; ww < 8; ww++) {
            ll += sm_l[ww][g];
            float4 t = sm_acc[ww][g][ln];
            aa.x += t.x; aa.y += t.y; aa.z += t.z; aa.w += t.w;
        }
        if (ln == 0) pbase[4 + g] = ll;
        ((float4*)(pbase + 8))[g * 32 + ln] = aa;
    }
}

// ------------------------- attention combine --------------------------------
// grid: B*NKV = 256, block 128. Plain sum of active chunks (fixed reference).
__global__ void __launch_bounds__(128) attn_combine_kernel(const int* __restrict__ positions) {
    int x = blockIdx.x;                 // b*8 + kv
    int b = x >> 3;
    int L = positions[b] + 1;
    int nc = min(NCHUNK, (L + CHUNK - 1) / CHUNK);
    int g = threadIdx.x >> 5;
    int ln = threadIdx.x & 31;
    const float* base0 = g_attn_part + (size_t)x * NCHUNK * PART_STRIDE;

    float ll = 0.f;
    float4 aa = make_float4(0.f, 0.f, 0.f, 0.f);
#pragma unroll
    for (int hw = 0; hw < 2; hw++) {
        float lv[8];
        float4 tv[8];
#pragma unroll
        for (int j = 0; j < 8; j++) {
            int c = hw * 8 + j;
            const float* base = base0 + (size_t)c * PART_STRIDE;
            if (c < nc) {
                lv[j] = base[4 + g];
                tv[j] = ((const float4*)(base + 8))[g * 32 + ln];
            } else {
                lv[j] = 0.f; tv[j] = make_float4(0.f, 0.f, 0.f, 0.f);
            }
        }
#pragma unroll
        for (int j = 0; j < 8; j++) {
            ll += lv[j];
            aa.x += tv[j].x; aa.y += tv[j].y; aa.z += tv[j].z; aa.w += tv[j].w;
        }
    }
    float inv = 1.f / ll;
    ((float4*)g_attn_out)[(size_t)x * 128 + g * 32 + ln] =
        make_float4(aa.x * inv, aa.y * inv, aa.z * inv, aa.w * inv);
}

// ------------------------- final split-K reduce ------------------------------
__global__ void __launch_bounds__(256) add_out_kernel(float* __restrict__ out) {
    int i = blockIdx.x * 256 + threadIdx.x;       // float4 index, 32768 total
    float4 s = make_float4(0.f, 0.f, 0.f, 0.f);
#pragma unroll
    for (int j = 0; j < SPLITK; j++) {
        float4 t = ((const float4*)g_part)[(size_t)j * (B_ * HID_ / 4) + i];
        s.x += t.x; s.y += t.y; s.z += t.z; s.w += t.w;
    }
    ((float4*)out)[i] = s;
}

// ------------------------- launch ------------------------------------------
extern "C" void kernel_launch(void* const* d_in, const int* in_sizes, int n_in,
                              void* d_out, int out_size) {
    const float* hidden = 0; const float* w_qkv = 0; const float* w_o = 0;
    const float* k_cache = 0; const float* v_cache = 0;
    const int* positions = 0; const int* btables = 0;
    for (int i = 0; i < n_in; i++) {
        int sz = in_sizes[i];
        if (sz == B_ * HID_)               hidden  = (const float*)d_in[i];
        else if (sz == HID_ * QKV_N)       w_qkv   = (const float*)d_in[i];
        else if (sz == NH_ * HD_ * HID_)   w_o     = (const float*)d_in[i];
        else if (sz == 4096 * BS_ * NKV_ * HD_) {
            if (!k_cache) k_cache = (const float*)d_in[i];
            else if (!v_cache) v_cache = (const float*)d_in[i];
        }
        else if (sz == B_) { if (!positions) positions = (const int*)d_in[i]; }
        else if (sz == B_ * MAXB_)         btables = (const int*)d_in[i];
    }
    float* out = (float*)d_out;

    // two no-ops so the ncu capture window (launch #4) lands on gemm1
    noop_kernel<<<1, 32>>>();
    noop_kernel<<<1, 32>>>();
    // 1. qkv = hidden @ w_qkv  (3xTF32 mma, split-K=16, cp.async W pipeline)
    prep_frag_kernel<<<512, 256>>>(hidden);
    gemm_mma3_kernel<<<dim3(QKV_N / GNT, SPLITK), 128>>>(w_qkv, QKV_N);
    // 2. combine + RoPE
    rope_qk_kernel<<<B_ * 10, 128>>>(positions);
    rope_v_kernel<<<B_ * 2, 128>>>();
    // 3. paged attention (flash-decode partials + combine)
    attn_partial_kernel<<<B_ * NKV_ * NCHUNK, 256>>>(k_cache, v_cache, positions, btables);
    attn_combine_kernel<<<B_ * NKV_, 128>>>(positions);
    // 4. out = attn @ w_o
    prep_frag_attn_kernel<<<512, 256>>>();
    gemm_mma3_kernel<<<dim3(HID_ / GNT, SPLITK), 128>>>(w_o, HID_);
    add_out_kernel<<<B_ * HID_ / 4 / 256, 256>>>(out);
}

// round 14
// speedup vs baseline: 1.0060x; 1.0058x over previous
#include <cuda_runtime.h>
#include <cuda_bf16.h>
#include <math.h>

// Problem constants
#define B_    32
#define HID_  4096
#define NH_   32
#define NKV_  8
#define HD_   128
#define BS_   16
#define MAXB_ 128
#define S_    2048
#define QKV_N 6144           // (NH + 2*NKV) * HD
#define NCHUNK 16            // flash-decode chunks of 128 keys
#define CHUNK 128
#define PART_STRIDE 528      // floats per attention partial record (16B aligned)

#define SPLITK 16            // GEMM split-K
#define GSLICE 256           // K rows per split slice (4096/16)
#define GNCH   16            // 16-row chunks per slice
#define GNT    128           // N cols per GEMM block (4 warps x n32)
#define WROW   40            // per-warp smem row stride (floats) -> conflict-free
#define WSTG   (16 * WROW)   // floats per stage (640)
#define WREG   (4 * WSTG)    // floats per warp region (2560)

// ------------------------- scratch (device globals) -------------------------
// Referenced ONLY inside device code (host-side symbol decay = round-0 bug).
__device__ __align__(16) float g_fragA_hi[B_ * HID_];         // tf32-hi A fragments
__device__ __align__(16) float g_fragA_lo[B_ * HID_];         // tf32-lo A fragments
__device__ __align__(16) float g_part[SPLITK * B_ * QKV_N];   // split-K partials
__device__ __align__(16) float g_qkv[B_ * QKV_N];             // roped qkv
__device__ __align__(16) float g_attn_part[B_ * NKV_ * NCHUNK * PART_STRIDE];
__device__ __align__(16) float g_attn_out[B_ * NH_ * HD_];

// ------------------------- helpers ------------------------------------------
__device__ __forceinline__ unsigned tf32u(float x) {
    unsigned r;
    asm("cvt.rna.tf32.f32 %0, %1;" : "=r"(r) : "f"(x));
    return r;
}

__device__ __forceinline__ void mma8(float acc[4], float4 a, unsigned b0, unsigned b1) {
    asm volatile(
        "mma.sync.aligned.m16n8k8.row.col.f32.tf32.tf32.f32 "
        "{%0,%1,%2,%3},{%4,%5,%6,%7},{%8,%9},{%0,%1,%2,%3};"
        : "+f"(acc[0]), "+f"(acc[1]), "+f"(acc[2]), "+f"(acc[3])
        : "r"(__float_as_uint(a.x)), "r"(__float_as_uint(a.y)),
          "r"(__float_as_uint(a.z)), "r"(__float_as_uint(a.w)),
          "r"(b0), "r"(b1));
}

// no-op: shifts the ncu capture window so launch #4 = gemm1
__global__ void noop_kernel() {}

// ------------------------- A-fragment prep (R4-verified layout) -------------
__global__ void __launch_bounds__(256) prep_frag_kernel(const float* __restrict__ A) {
    int idx = blockIdx.x * 256 + threadIdx.x;          // 131072 total
    int i    = idx & 3;
    int lane = (idx >> 2) & 31;
    int mt   = (idx >> 7) & 1;
    int k8   = idx >> 8;
    int row = mt * 16 + (lane >> 2) + (i & 1) * 8;
    int col = k8 * 8 + (lane & 3) + (i >> 1) * 4;
    float v = A[row * HID_ + col];
    float hi = __uint_as_float(tf32u(v));
    float lo = __uint_as_float(tf32u(v - hi));
    g_fragA_hi[idx] = hi;
    g_fragA_lo[idx] = lo;
}

__global__ void __launch_bounds__(256) prep_frag_attn_kernel() {
    int idx = blockIdx.x * 256 + threadIdx.x;
    int i    = idx & 3;
    int lane = (idx >> 2) & 31;
    int mt   = (idx >> 7) & 1;
    int k8   = idx >> 8;
    int row = mt * 16 + (lane >> 2) + (i & 1) * 8;
    int col = k8 * 8 + (lane & 3) + (i >> 1) * 4;
    float v = g_attn_out[row * (NH_ * HD_) + col];
    float hi = __uint_as_float(tf32u(v));
    float lo = __uint_as_float(tf32u(v - hi));
    g_fragA_hi[idx] = hi;
    g_fragA_lo[idx] = lo;
}

// ------------------------- 3xTF32 tensor-core GEMM (BARRIER-FREE) -----------
// C[32,N] = A[32,4096] @ W[4096,N].  grid (N/GNT, SPLITK), block 128 (4 warps).
// Each warp owns a disjoint 32-col W slice with a PRIVATE 4-stage cp.async
// ring; no __syncthreads in the mainloop — warps self-pace (attn-style).
__global__ void __launch_bounds__(128, 4) gemm_mma3_kernel(
    const float* __restrict__ W, int N)
{
    __shared__ float sW[4 * WREG];        // 40 KB: 4 warps x 4 stages x 16x40
    int tid = threadIdx.x;
    int w = tid >> 5, lane = tid & 31;
    int nb = blockIdx.x, kb = blockIdx.y;
    int n0 = nb * GNT;
    int k0 = kb * GSLICE;
    int k8base = k0 >> 3;

    unsigned sbase;
    asm("{ .reg .u64 t; cvta.to.shared.u64 t, %1; cvt.u32.u64 %0, t; }"
        : "=r"(sbase) : "l"(sW));
    unsigned wbase = sbase + (unsigned)(w * WREG) * 4u;   // this warp's region
    const float* wsrc0 = W + (size_t)k0 * N + n0 + w * 32;

    // per-warp stage: 16 rows x 32 cols; 128 x 16B ops, 4 per lane.
    int srow[4], sseg[4];
#pragma unroll
    for (int p = 0; p < 4; p++) {
        int f = p * 32 + lane;
        srow[p] = f >> 3;                 // 0..15
        sseg[p] = f & 7;                  // 16B segment within the 128B row
    }

#define STAGE(C) do { int _c = (C);                                          \
        unsigned _sb = wbase + (unsigned)((_c & 3) * WSTG) * 4u;              \
        const float* _src = wsrc0 + (size_t)(_c * 16) * N;                    \
        _Pragma("unroll")                                                     \
        for (int _p = 0; _p < 4; _p++) {                                      \
            unsigned _dst = _sb + (unsigned)(srow[_p] * WROW + sseg[_p] * 4) * 4u; \
            const float* _g = _src + (size_t)srow[_p] * N + sseg[_p] * 4;     \
            asm volatile("cp.async.cg.shared.global [%0], [%1], 16;"          \
                         :: "r"(_dst), "l"(_g));                              \
        }                                                                     \
        asm volatile("cp.async.commit_group;"); } while (0)

    float acc[2][4][4];
#pragma unroll
    for (int mf = 0; mf < 2; mf++)
#pragma unroll
        for (int nf = 0; nf < 4; nf++)
#pragma unroll
            for (int i = 0; i < 4; i++) acc[mf][nf][i] = 0.f;

    const float4* fhi = (const float4*)g_fragA_hi;
    const float4* flo = (const float4*)g_fragA_lo;

    // prefetch k8 #0 A fragments
    float4 nah0 = __ldg(&fhi[(size_t)(k8base * 2 + 0) * 32 + lane]);
    float4 nah1 = __ldg(&fhi[(size_t)(k8base * 2 + 1) * 32 + lane]);
    float4 nal0 = __ldg(&flo[(size_t)(k8base * 2 + 0) * 32 + lane]);
    float4 nal1 = __ldg(&flo[(size_t)(k8base * 2 + 1) * 32 + lane]);

    STAGE(0); STAGE(1); STAGE(2);

    const float* swarp = sW + w * WREG;

    for (int kk = 0; kk < 32; kk++) {
        if ((kk & 1) == 0) {                        // chunk boundary (per-warp!)
            int c = kk >> 1;
            int rem = GNCH - 1 - c;
            if (rem >= 2)      asm volatile("cp.async.wait_group 2;" ::: "memory");
            else if (rem == 1) asm volatile("cp.async.wait_group 1;" ::: "memory");
            else               asm volatile("cp.async.wait_group 0;" ::: "memory");
            __syncwarp();
            if (c + 3 < GNCH) STAGE(c + 3);
        }

        // rotate prefetched A fragments; issue next k8's loads immediately
        float4 ah0 = nah0, ah1 = nah1, al0 = nal0, al1 = nal1;
        if (kk < 31) {
            int k8n = k8base + kk + 1;
            nah0 = __ldg(&fhi[(size_t)(k8n * 2 + 0) * 32 + lane]);
            nah1 = __ldg(&fhi[(size_t)(k8n * 2 + 1) * 32 + lane]);
            nal0 = __ldg(&flo[(size_t)(k8n * 2 + 0) * 32 + lane]);
            nal1 = __ldg(&flo[(size_t)(k8n * 2 + 1) * 32 + lane]);
        }

        // B fragment base: row = (kk&1)*8 + (lane&3), col = (lane>>2)
        const float* sb = swarp + ((kk >> 1) & 3) * WSTG
                        + ((kk & 1) * 8 + (lane & 3)) * WROW + (lane >> 2);

        // gather + convert all 4 B fragment pairs (conflict-free LDS)
        unsigned b0h[4], b1h[4], b0l[4], b1l[4];
#pragma unroll
        for (int nf = 0; nf < 4; nf++) {
            float b0 = sb[nf * 8];
            float b1 = sb[nf * 8 + 4 * WROW];
            b0h[nf] = tf32u(b0); b1h[nf] = tf32u(b1);
            b0l[nf] = tf32u(b0 - __uint_as_float(b0h[nf]));
            b1l[nf] = tf32u(b1 - __uint_as_float(b1h[nf]));
        }
        // 3 passes of 8 independent accumulators
#pragma unroll
        for (int nf = 0; nf < 4; nf++) mma8(acc[0][nf], ah0, b0h[nf], b1h[nf]);
#pragma unroll
        for (int nf = 0; nf < 4; nf++) mma8(acc[1][nf], ah1, b0h[nf], b1h[nf]);
#pragma unroll
        for (int nf = 0; nf < 4; nf++) mma8(acc[0][nf], al0, b0h[nf], b1h[nf]);
#pragma unroll
        for (int nf = 0; nf < 4; nf++) mma8(acc[1][nf], al1, b0h[nf], b1h[nf]);
#pragma unroll
        for (int nf = 0; nf < 4; nf++) mma8(acc[0][nf], ah0, b0l[nf], b1l[nf]);
#pragma unroll
        for (int nf = 0; nf < 4; nf++) mma8(acc[1][nf], ah1, b0l[nf], b1l[nf]);
    }
#undef STAGE

    // writeback (R4-verified accumulator layout)
    float* op = g_part + (size_t)kb * 32 * N + n0 + w * 32;
    int r = lane >> 2, c2 = (lane & 3) * 2;
#pragma unroll
    for (int mf = 0; mf < 2; mf++)
#pragma unroll
        for (int nf = 0; nf < 4; nf++) {
            *(float2*)(op + (size_t)(mf * 16 + r    ) * N + nf * 8 + c2) =
                make_float2(acc[mf][nf][0], acc[mf][nf][1]);
            *(float2*)(op + (size_t)(mf * 16 + r + 8) * N + nf * 8 + c2) =
                make_float2(acc[mf][nf][2], acc[mf][nf][3]);
        }
}

// ------------------------- split-K sum + RoPE (q,k heads) -------------------
// grid: 320 = 32 b x 10 col-groups of 512. block 128.
__global__ void __launch_bounds__(128) rope_qk_kernel(const int* __restrict__ positions) {
    __shared__ float sq[512];
    __shared__ float scs[64], ssn[64];
    int blk = blockIdx.x;
    int grp = blk % 10;                 // 512-col group (4 heads)
    int b   = blk / 10;
    int tid = threadIdx.x;
    int pos = positions[b];
    int cbase = grp * 512;

    {
        int i4 = cbase / 4 + tid;
        float4 s = make_float4(0.f, 0.f, 0.f, 0.f);
#pragma unroll
        for (int j = 0; j < SPLITK; j++) {
            float4 t = ((const float4*)(g_part + (size_t)j * 32 * QKV_N + (size_t)b * QKV_N))[i4];
            s.x += t.x; s.y += t.y; s.z += t.z; s.w += t.w;
        }
        ((float4*)sq)[tid] = s;
    }
    if (tid < 64) {
        const double LOG_THETA_OVER_HALF = 0.20503692777194265;  // ln(500000)/64
        double inv = exp(-(double)tid * LOG_THETA_OVER_HALF);
        double f = (double)pos * inv;
        double sd, cd;
        sincos(f, &sd, &cd);
        scs[tid] = (float)cd; ssn[tid] = (float)sd;
    }
    __syncthreads();

    float* out = g_qkv + (size_t)b * QKV_N + cbase;
#pragma unroll
    for (int r = 0; r < 2; r++) {
        int p = tid + r * 128;
        int h = p >> 6, d = p & 63;
        int c1 = h * 128 + d, c2 = c1 + 64;
        float x1 = sq[c1], x2 = sq[c2];
        float cs = scs[d], sn = ssn[d];
        out[c1] = x1 * cs - x2 * sn;
        out[c2] = x2 * cs + x1 * sn;
    }
}

// ------------------------- split-K sum, v passthrough ------------------------
// grid: 64 = 32 b x 2 groups. block 128.
__global__ void __launch_bounds__(128) rope_v_kernel() {
    int blk = blockIdx.x;
    int grp = blk & 1;
    int b   = blk >> 1;
    int tid = threadIdx.x;
    int i4 = (5120 + grp * 512) / 4 + tid;
    float4 s = make_float4(0.f, 0.f, 0.f, 0.f);
#pragma unroll
    for (int j = 0; j < SPLITK; j++) {
        float4 t = ((const float4*)(g_part + (size_t)j * 32 * QKV_N + (size_t)b * QKV_N))[i4];
        s.x += t.x; s.y += t.y; s.z += t.z; s.w += t.w;
    }
    ((float4*)(g_qkv + (size_t)b * QKV_N))[i4] = s;
}

// ------------------------- attention partial (flash-decode) -----------------
// grid: B*NKV*NCHUNK = 4096, block 256 (8 warps, warp-per-key-pair).
__global__ void __launch_bounds__(256, 3) attn_partial_kernel(
    const float* __restrict__ kc, const float* __restrict__ vc,
    const int* __restrict__ positions, const int* __restrict__ bt)
{
    int x = blockIdx.x;
    int c  = x & (NCHUNK - 1);
    int kv = (x >> 4) & 7;
    int b  = x >> 7;
    int tid = threadIdx.x;
    int pos = positions[b];
    int L = pos + 1;
    int s0 = c * CHUNK;
    if (s0 >= L) return;                 // empty chunk: combine skips it
    int s1 = min(s0 + CHUNK, L);
    int sEnd = min(s1, pos);             // cache keys strictly below pos
    bool hasNew = (pos < s1);            // this chunk owns the new token

    float* pbase = g_attn_part + (size_t)x * PART_STRIDE;

    __shared__ int sbt[8];               // block-table slice for 128-key chunk
    if (tid < 8) sbt[tid] = bt[b * MAXB_ + (s0 >> 4) + tid];
    __syncthreads();

    int w = tid >> 5, lane = tid & 31;
    bool b1 = (lane & 1), b2 = (lane & 2), b4 = (lane & 4);
    const float4* qp = (const float4*)(g_qkv + (size_t)b * QKV_N + kv * 512);
    const float SCALE = 0.08838834764831845f;   // 1/sqrt(128)
    float4 q[4];
#pragma unroll
    for (int g = 0; g < 4; g++) {
        float4 t = qp[g * 32 + lane];
        q[g] = make_float4(t.x * SCALE, t.y * SCALE, t.z * SCALE, t.w * SCALE);
    }
    const float4* knew = (const float4*)(g_qkv + (size_t)b * QKV_N + 4096 + kv * 128);
    const float4* vnew = (const float4*)(g_qkv + (size_t)b * QKV_N + 5120 + kv * 128);

    const float* kcb = kc + (size_t)kv * 128 + lane * 4;
    const float* vcb = vc + (size_t)kv * 128 + lane * 4;

    float l1 = 0.f;
    float4 acc[4];
#pragma unroll
    for (int g = 0; g < 4; g++) acc[g] = make_float4(0.f, 0.f, 0.f, 0.f);

#define LOADQ(I, SX) do { int _s = (SX);                                   \
        if (_s < sEnd) {                                                   \
            int _slot = sbt[(_s - s0) >> 4] * 16 + (_s & 15);              \
            const float* _kp = kcb + ((size_t)_slot << 10);                \
            const float* _vp = vcb + ((size_t)_slot << 10);                \
            asm volatile("ld.global.cg.v4.f32 {%0,%1,%2,%3}, [%4];"        \
                : "=f"(kq[I].x), "=f"(kq[I].y), "=f"(kq[I].z), "=f"(kq[I].w) \
                : "l"(_kp));                                               \
            asm volatile("ld.global.cg.v4.f32 {%0,%1,%2,%3}, [%4];"        \
                : "=f"(vq[I].x), "=f"(vq[I].y), "=f"(vq[I].z), "=f"(vq[I].w) \
                : "l"(_vp));                                               \
        } } while (0)

#define STEP2(kkA, vvA, kkB, vvB, useB) do {                               \
        float a0 = fmaf(q[0].x, kkA.x, fmaf(q[0].y, kkA.y, fmaf(q[0].z, kkA.z, q[0].w * kkA.w))); \
        float a1 = fmaf(q[1].x, kkA.x, fmaf(q[1].y, kkA.y, fmaf(q[1].z, kkA.z, q[1].w * kkA.w))); \
        float a2 = fmaf(q[2].x, kkA.x, fmaf(q[2].y, kkA.y, fmaf(q[2].z, kkA.z, q[2].w * kkA.w))); \
        float a3 = fmaf(q[3].x, kkA.x, fmaf(q[3].y, kkA.y, fmaf(q[3].z, kkA.z, q[3].w * kkA.w))); \
        float c0 = fmaf(q[0].x, kkB.x, fmaf(q[0].y, kkB.y, fmaf(q[0].z, kkB.z, q[0].w * kkB.w))); \
        float c1 = fmaf(q[1].x, kkB.x, fmaf(q[1].y, kkB.y, fmaf(q[1].z, kkB.z, q[1].w * kkB.w))); \
        float c2 = fmaf(q[2].x, kkB.x, fmaf(q[2].y, kkB.y, fmaf(q[2].z, kkB.z, q[2].w * kkB.w))); \
        float c3 = fmaf(q[3].x, kkB.x, fmaf(q[3].y, kkB.y, fmaf(q[3].z, kkB.z, q[3].w * kkB.w))); \
        float vA01 = (b1 ? a1 : a0) + __shfl_xor_sync(0xffffffffu, b1 ? a0 : a1, 1); \
        float vA23 = (b1 ? a3 : a2) + __shfl_xor_sync(0xffffffffu, b1 ? a2 : a3, 1); \
        float vB01 = (b1 ? c1 : c0) + __shfl_xor_sync(0xffffffffu, b1 ? c0 : c1, 1); \
        float vB23 = (b1 ? c3 : c2) + __shfl_xor_sync(0xffffffffu, b1 ? c2 : c3, 1); \
        float vA = (b2 ? vA23 : vA01) + __shfl_xor_sync(0xffffffffu, b2 ? vA01 : vA23, 2); \
        float vB = (b2 ? vB23 : vB01) + __shfl_xor_sync(0xffffffffu, b2 ? vB01 : vB23, 2); \
        float vv_ = (b4 ? vB : vA) + __shfl_xor_sync(0xffffffffu, b4 ? vA : vB, 4); \
        vv_ += __shfl_xor_sync(0xffffffffu, vv_, 8);                       \
        vv_ += __shfl_xor_sync(0xffffffffu, vv_, 16);                      \
        float px = __expf(vv_);                                            \
        if (b4 && !(useB)) px = 0.f;                                       \
        l1 += px;                                                          \
        float pA0 = __shfl_sync(0xffffffffu, px, 0, 8);                    \
        float pA1 = __shfl_sync(0xffffffffu, px, 1, 8);                    \
        float pA2 = __shfl_sync(0xffffffffu, px, 2, 8);                    \
        float pA3 = __shfl_sync(0xffffffffu, px, 3, 8);                    \
        float pB0 = __shfl_sync(0xffffffffu, px, 4, 8);                    \
        float pB1 = __shfl_sync(0xffffffffu, px, 5, 8);                    \
        float pB2 = __shfl_sync(0xffffffffu, px, 6, 8);                    \
        float pB3 = __shfl_sync(0xffffffffu, px, 7, 8);                    \
        acc[0].x = fmaf(pA0, vvA.x, fmaf(pB0, vvB.x, acc[0].x));           \
        acc[0].y = fmaf(pA0, vvA.y, fmaf(pB0, vvB.y, acc[0].y));           \
        acc[0].z = fmaf(pA0, vvA.z, fmaf(pB0, vvB.z, acc[0].z));           \
        acc[0].w = fmaf(pA0, vvA.w, fmaf(pB0, vvB.w, acc[0].w));           \
        acc[1].x = fmaf(pA1, vvA.x, fmaf(pB1, vvB.x, acc[1].x));           \
        acc[1].y = fmaf(pA1, vvA.y, fmaf(pB1, vvB.y, acc[1].y));           \
        acc[1].z = fmaf(pA1, vvA.z, fmaf(pB1, vvB.z, acc[1].z));           \
        acc[1].w = fmaf(pA1, vvA.w, fmaf(pB1, vvB.w, acc[1].w));           \
        acc[2].x = fmaf(pA2, vvA.x, fmaf(pB2, vvB.x, acc[2].x));           \
        acc[2].y = fmaf(pA2, vvA.y, fmaf(pB2, vvB.y, acc[2].y));           \
        acc[2].z = fmaf(pA2, vvA.z, fmaf(pB2, vvB.z, acc[2].z));           \
        acc[2].w = fmaf(pA2, vvA.w, fmaf(pB2, vvB.w, acc[2].w));           \
        acc[3].x = fmaf(pA3, vvA.x, fmaf(pB3, vvB.x, acc[3].x));           \
        acc[3].y = fmaf(pA3, vvA.y, fmaf(pB3, vvB.y, acc[3].y));           \
        acc[3].z = fmaf(pA3, vvA.z, fmaf(pB3, vvB.z, acc[3].z));           \
        acc[3].w = fmaf(pA3, vvA.w, fmaf(pB3, vvB.w, acc[3].w));           \
    } while (0)

    float4 kq[2], vq[2];
#pragma unroll
    for (int i = 0; i < 2; i++) { kq[i] = make_float4(0,0,0,0); vq[i] = kq[i]; }
    int s = s0 + w;
    LOADQ(0, s); LOADQ(1, s + 8);

    for (; s < sEnd; s += 16) {
        float4 kkA = kq[0], vvA = vq[0], kkB = kq[1], vvB = vq[1];
        bool useB = (s + 8 < sEnd);      // warp-uniform
        LOADQ(0, s + 16); LOADQ(1, s + 24);
        STEP2(kkA, vvA, kkB, vvB, useB);
    }

    if (hasNew && w == 0) {
        float4 kk = knew[lane], vv = vnew[lane];
        float4 zz = make_float4(0.f, 0.f, 0.f, 0.f);
        STEP2(kk, vv, zz, zz, false);
    }
#undef LOADQ
#undef STEP2

    l1 += __shfl_xor_sync(0xffffffffu, l1, 4);

    __shared__ float sm_l[8][4];
    __shared__ float4 sm_acc[8][4][32];
    if (lane < 4) sm_l[w][lane] = l1;
#pragma unroll
    for (int g = 0; g < 4; g++) sm_acc[w][g][lane] = acc[g];
    __syncthreads();

    if (tid < 128) {
        int g = tid >> 5;
        int ln = tid & 31;
        float ll = 0.f;
        float4 aa = make_float4(0.f, 0.f, 0.f, 0.f);
#pragma unroll
        for (int ww = 0; ww < 8; ww++) {
            ll += sm_l[ww][g];
            float4 t = sm_acc[ww][g][ln];
            aa.x += t.x; aa.y += t.y; aa.z += t.z; aa.w += t.w;
        }
        if (ln == 0) pbase[4 + g] = ll;
        ((float4*)(pbase + 8))[g * 32 + ln] = aa;
    }
}

// ------------------------- attention combine --------------------------------
// grid: B*NKV = 256, block 128. Plain sum of active chunks (fixed reference).
__global__ void __launch_bounds__(128) attn_combine_kernel(const int* __restrict__ positions) {
    int x = blockIdx.x;                 // b*8 + kv
    int b = x >> 3;
    int L = positions[b] + 1;
    int nc = min(NCHUNK, (L + CHUNK - 1) / CHUNK);
    int g = threadIdx.x >> 5;
    int ln = threadIdx.x & 31;
    const float* base0 = g_attn_part + (size_t)x * NCHUNK * PART_STRIDE;

    float ll = 0.f;
    float4 aa = make_float4(0.f, 0.f, 0.f, 0.f);
#pragma unroll
    for (int hw = 0; hw < 2; hw++) {
        float lv[8];
        float4 tv[8];
#pragma unroll
        for (int j = 0; j < 8; j++) {
            int c = hw * 8 + j;
            const float* base = base0 + (size_t)c * PART_STRIDE;
            if (c < nc) {
                lv[j] = base[4 + g];
                tv[j] = ((const float4*)(base + 8))[g * 32 + ln];
            } else {
                lv[j] = 0.f; tv[j] = make_float4(0.f, 0.f, 0.f, 0.f);
            }
        }
#pragma unroll
        for (int j = 0; j < 8; j++) {
            ll += lv[j];
            aa.x += tv[j].x; aa.y += tv[j].y; aa.z += tv[j].z; aa.w += tv[j].w;
        }
    }
    float inv = 1.f / ll;
    ((float4*)g_attn_out)[(size_t)x * 128 + g * 32 + ln] =
        make_float4(aa.x * inv, aa.y * inv, aa.z * inv, aa.w * inv);
}

// ------------------------- final split-K reduce ------------------------------
__global__ void __launch_bounds__(256) add_out_kernel(float* __restrict__ out) {
    int i = blockIdx.x * 256 + threadIdx.x;       // float4 index, 32768 total
    float4 s = make_float4(0.f, 0.f, 0.f, 0.f);
#pragma unroll
    for (int j = 0; j < SPLITK; j++) {
        float4 t = ((const float4*)g_part)[(size_t)j * (B_ * HID_ / 4) + i];
        s.x += t.x; s.y += t.y; s.z += t.z; s.w += t.w;
    }
    ((float4*)out)[i] = s;
}

// ------------------------- launch ------------------------------------------
extern "C" void kernel_launch(void* const* d_in, const int* in_sizes, int n_in,
                              void* d_out, int out_size) {
    const float* hidden = 0; const float* w_qkv = 0; const float* w_o = 0;
    const float* k_cache = 0; const float* v_cache = 0;
    const int* positions = 0; const int* btables = 0;
    for (int i = 0; i < n_in; i++) {
        int sz = in_sizes[i];
        if (sz == B_ * HID_)               hidden  = (const float*)d_in[i];
        else if (sz == HID_ * QKV_N)       w_qkv   = (const float*)d_in[i];
        else if (sz == NH_ * HD_ * HID_)   w_o     = (const float*)d_in[i];
        else if (sz == 4096 * BS_ * NKV_ * HD_) {
            if (!k_cache) k_cache = (const float*)d_in[i];
            else if (!v_cache) v_cache = (const float*)d_in[i];
        }
        else if (sz == B_) { if (!positions) positions = (const int*)d_in[i]; }
        else if (sz == B_ * MAXB_)         btables = (const int*)d_in[i];
    }
    float* out = (float*)d_out;

    // two no-ops so the ncu capture window (launch #4) lands on gemm1
    noop_kernel<<<1, 32>>>();
    noop_kernel<<<1, 32>>>();
    // 1. qkv = hidden @ w_qkv  (3xTF32 mma, split-K=16, per-warp cp.async ring)
    prep_frag_kernel<<<512, 256>>>(hidden);
    gemm_mma3_kernel<<<dim3(QKV_N / GNT, SPLITK), 128>>>(w_qkv, QKV_N);
    // 2. combine + RoPE
    rope_qk_kernel<<<B_ * 10, 128>>>(positions);
    rope_v_kernel<<<B_ * 2, 128>>>();
    // 3. paged attention (flash-decode partials + combine)
    attn_partial_kernel<<<B_ * NKV_ * NCHUNK, 256>>>(k_cache, v_cache, positions, btables);
    attn_combine_kernel<<<B_ * NKV_, 128>>>(positions);
    // 4. out = attn @ w_o
    prep_frag_attn_kernel<<<512, 256>>>();
    gemm_mma3_kernel<<<dim3(HID_ / GNT, SPLITK), 128>>>(w_o, HID_);
    add_out_kernel<<<B_ * HID_ / 4 / 256, 256>>>(out);
}

// round 15
// speedup vs baseline: 1.0123x; 1.0063x over previous
#include <cuda_runtime.h>
#include <cuda_bf16.h>
#include <math.h>

// Problem constants
#define B_    32
#define HID_  4096
#define NH_   32
#define NKV_  8
#define HD_   128
#define BS_   16
#define MAXB_ 128
#define S_    2048
#define QKV_N 6144           // (NH + 2*NKV) * HD
#define NCHUNK 16            // flash-decode chunks of 128 keys
#define CHUNK 128
#define PART_STRIDE 528      // floats per attention partial record (16B aligned)

#define SPLITK 16            // GEMM split-K
#define GSLICE 256           // K rows per split slice (4096/16)
#define GNCH   16            // 16-row chunks per slice
#define GNT    128           // N cols per GEMM block (4 warps x n32)
#define WROW   40            // per-warp smem row stride (floats) -> conflict-free
#define WSTG   (16 * WROW)   // floats per stage (640)
#define WREG   (4 * WSTG)    // floats per warp region (2560)

// ------------------------- scratch (device globals) -------------------------
// Referenced ONLY inside device code (host-side symbol decay = round-0 bug).
__device__ __align__(16) float g_fragA_hi[B_ * HID_];         // tf32-hi A fragments
__device__ __align__(16) float g_fragA_lo[B_ * HID_];         // tf32-lo A fragments
__device__ __align__(16) float g_part[SPLITK * B_ * QKV_N];   // split-K partials
__device__ __align__(16) float g_qkv[B_ * QKV_N];             // roped qkv
__device__ __align__(16) float g_attn_part[B_ * NKV_ * NCHUNK * PART_STRIDE];
__device__ __align__(16) float g_attn_out[B_ * NH_ * HD_];

// ------------------------- helpers ------------------------------------------
__device__ __forceinline__ unsigned tf32u(float x) {
    unsigned r;
    asm("cvt.rna.tf32.f32 %0, %1;" : "=r"(r) : "f"(x));
    return r;
}

__device__ __forceinline__ void mma8(float acc[4], float4 a, unsigned b0, unsigned b1) {
    asm volatile(
        "mma.sync.aligned.m16n8k8.row.col.f32.tf32.tf32.f32 "
        "{%0,%1,%2,%3},{%4,%5,%6,%7},{%8,%9},{%0,%1,%2,%3};"
        : "+f"(acc[0]), "+f"(acc[1]), "+f"(acc[2]), "+f"(acc[3])
        : "r"(__float_as_uint(a.x)), "r"(__float_as_uint(a.y)),
          "r"(__float_as_uint(a.z)), "r"(__float_as_uint(a.w)),
          "r"(b0), "r"(b1));
}

// no-op: shifts the ncu capture window so launch #4 = gemm1
__global__ void noop_kernel() {}

// ------------------------- A-fragment prep (R4-verified layout) -------------
__global__ void __launch_bounds__(256) prep_frag_kernel(const float* __restrict__ A) {
    int idx = blockIdx.x * 256 + threadIdx.x;          // 131072 total
    int i    = idx & 3;
    int lane = (idx >> 2) & 31;
    int mt   = (idx >> 7) & 1;
    int k8   = idx >> 8;
    int row = mt * 16 + (lane >> 2) + (i & 1) * 8;
    int col = k8 * 8 + (lane & 3) + (i >> 1) * 4;
    float v = A[row * HID_ + col];
    float hi = __uint_as_float(tf32u(v));
    float lo = __uint_as_float(tf32u(v - hi));
    g_fragA_hi[idx] = hi;
    g_fragA_lo[idx] = lo;
}

__global__ void __launch_bounds__(256) prep_frag_attn_kernel() {
    int idx = blockIdx.x * 256 + threadIdx.x;
    int i    = idx & 3;
    int lane = (idx >> 2) & 31;
    int mt   = (idx >> 7) & 1;
    int k8   = idx >> 8;
    int row = mt * 16 + (lane >> 2) + (i & 1) * 8;
    int col = k8 * 8 + (lane & 3) + (i >> 1) * 4;
    float v = g_attn_out[row * (NH_ * HD_) + col];
    float hi = __uint_as_float(tf32u(v));
    float lo = __uint_as_float(tf32u(v - hi));
    g_fragA_hi[idx] = hi;
    g_fragA_lo[idx] = lo;
}

// ------------------------- 3xTF32 tensor-core GEMM (BARRIER-FREE) -----------
// C[32,N] = A[32,4096] @ W[4096,N].  grid (N/GNT, SPLITK), block 128 (4 warps).
// Each warp owns a disjoint 32-col W slice with a PRIVATE 4-stage cp.async
// ring; no __syncthreads in the mainloop — warps self-pace (attn-style).
__global__ void __launch_bounds__(128, 4) gemm_mma3_kernel(
    const float* __restrict__ W, int N)
{
    __shared__ float sW[4 * WREG];        // 40 KB: 4 warps x 4 stages x 16x40
    int tid = threadIdx.x;
    int w = tid >> 5, lane = tid & 31;
    int nb = blockIdx.x, kb = blockIdx.y;
    int n0 = nb * GNT;
    int k0 = kb * GSLICE;
    int k8base = k0 >> 3;

    unsigned sbase;
    asm("{ .reg .u64 t; cvta.to.shared.u64 t, %1; cvt.u32.u64 %0, t; }"
        : "=r"(sbase) : "l"(sW));
    unsigned wbase = sbase + (unsigned)(w * WREG) * 4u;   // this warp's region
    const float* wsrc0 = W + (size_t)k0 * N + n0 + w * 32;

    // per-warp stage: 16 rows x 32 cols; 128 x 16B ops, 4 per lane.
    int srow[4], sseg[4];
#pragma unroll
    for (int p = 0; p < 4; p++) {
        int f = p * 32 + lane;
        srow[p] = f >> 3;                 // 0..15
        sseg[p] = f & 7;                  // 16B segment within the 128B row
    }

#define STAGE(C) do { int _c = (C);                                          \
        unsigned _sb = wbase + (unsigned)((_c & 3) * WSTG) * 4u;              \
        const float* _src = wsrc0 + (size_t)(_c * 16) * N;                    \
        _Pragma("unroll")                                                     \
        for (int _p = 0; _p < 4; _p++) {                                      \
            unsigned _dst = _sb + (unsigned)(srow[_p] * WROW + sseg[_p] * 4) * 4u; \
            const float* _g = _src + (size_t)srow[_p] * N + sseg[_p] * 4;     \
            asm volatile("cp.async.cg.shared.global [%0], [%1], 16;"          \
                         :: "r"(_dst), "l"(_g));                              \
        }                                                                     \
        asm volatile("cp.async.commit_group;"); } while (0)

    float acc[2][4][4];
#pragma unroll
    for (int mf = 0; mf < 2; mf++)
#pragma unroll
        for (int nf = 0; nf < 4; nf++)
#pragma unroll
            for (int i = 0; i < 4; i++) acc[mf][nf][i] = 0.f;

    const float4* fhi = (const float4*)g_fragA_hi;
    const float4* flo = (const float4*)g_fragA_lo;

    // prefetch k8 #0 A fragments
    float4 nah0 = __ldg(&fhi[(size_t)(k8base * 2 + 0) * 32 + lane]);
    float4 nah1 = __ldg(&fhi[(size_t)(k8base * 2 + 1) * 32 + lane]);
    float4 nal0 = __ldg(&flo[(size_t)(k8base * 2 + 0) * 32 + lane]);
    float4 nal1 = __ldg(&flo[(size_t)(k8base * 2 + 1) * 32 + lane]);

    STAGE(0); STAGE(1); STAGE(2);

    const float* swarp = sW + w * WREG;

    for (int kk = 0; kk < 32; kk++) {
        if ((kk & 1) == 0) {                        // chunk boundary (per-warp!)
            int c = kk >> 1;
            int rem = GNCH - 1 - c;
            if (rem >= 2)      asm volatile("cp.async.wait_group 2;" ::: "memory");
            else if (rem == 1) asm volatile("cp.async.wait_group 1;" ::: "memory");
            else               asm volatile("cp.async.wait_group 0;" ::: "memory");
            __syncwarp();
            if (c + 3 < GNCH) STAGE(c + 3);
        }

        // rotate prefetched A fragments; issue next k8's loads immediately
        float4 ah0 = nah0, ah1 = nah1, al0 = nal0, al1 = nal1;
        if (kk < 31) {
            int k8n = k8base + kk + 1;
            nah0 = __ldg(&fhi[(size_t)(k8n * 2 + 0) * 32 + lane]);
            nah1 = __ldg(&fhi[(size_t)(k8n * 2 + 1) * 32 + lane]);
            nal0 = __ldg(&flo[(size_t)(k8n * 2 + 0) * 32 + lane]);
            nal1 = __ldg(&flo[(size_t)(k8n * 2 + 1) * 32 + lane]);
        }

        // B fragment base: row = (kk&1)*8 + (lane&3), col = (lane>>2)
        const float* sb = swarp + ((kk >> 1) & 3) * WSTG
                        + ((kk & 1) * 8 + (lane & 3)) * WROW + (lane >> 2);

        // gather + convert all 4 B fragment pairs (conflict-free LDS)
        unsigned b0h[4], b1h[4], b0l[4], b1l[4];
#pragma unroll
        for (int nf = 0; nf < 4; nf++) {
            float b0 = sb[nf * 8];
            float b1 = sb[nf * 8 + 4 * WROW];
            b0h[nf] = tf32u(b0); b1h[nf] = tf32u(b1);
            b0l[nf] = tf32u(b0 - __uint_as_float(b0h[nf]));
            b1l[nf] = tf32u(b1 - __uint_as_float(b1h[nf]));
        }
        // 3 passes of 8 independent accumulators
#pragma unroll
        for (int nf = 0; nf < 4; nf++) mma8(acc[0][nf], ah0, b0h[nf], b1h[nf]);
#pragma unroll
        for (int nf = 0; nf < 4; nf++) mma8(acc[1][nf], ah1, b0h[nf], b1h[nf]);
#pragma unroll
        for (int nf = 0; nf < 4; nf++) mma8(acc[0][nf], al0, b0h[nf], b1h[nf]);
#pragma unroll
        for (int nf = 0; nf < 4; nf++) mma8(acc[1][nf], al1, b0h[nf], b1h[nf]);
#pragma unroll
        for (int nf = 0; nf < 4; nf++) mma8(acc[0][nf], ah0, b0l[nf], b1l[nf]);
#pragma unroll
        for (int nf = 0; nf < 4; nf++) mma8(acc[1][nf], ah1, b0l[nf], b1l[nf]);
    }
#undef STAGE

    // writeback (R4-verified accumulator layout)
    float* op = g_part + (size_t)kb * 32 * N + n0 + w * 32;
    int r = lane >> 2, c2 = (lane & 3) * 2;
#pragma unroll
    for (int mf = 0; mf < 2; mf++)
#pragma unroll
        for (int nf = 0; nf < 4; nf++) {
            *(float2*)(op + (size_t)(mf * 16 + r    ) * N + nf * 8 + c2) =
                make_float2(acc[mf][nf][0], acc[mf][nf][1]);
            *(float2*)(op + (size_t)(mf * 16 + r + 8) * N + nf * 8 + c2) =
                make_float2(acc[mf][nf][2], acc[mf][nf][3]);
        }
}

// ------------------------- split-K sum + RoPE (q,k heads) -------------------
// grid: 320 = 32 b x 10 col-groups of 512. block 128.
__global__ void __launch_bounds__(128) rope_qk_kernel(const int* __restrict__ positions) {
    __shared__ float sq[512];
    __shared__ float scs[64], ssn[64];
    int blk = blockIdx.x;
    int grp = blk % 10;                 // 512-col group (4 heads)
    int b   = blk / 10;
    int tid = threadIdx.x;
    int pos = positions[b];
    int cbase = grp * 512;

    {
        int i4 = cbase / 4 + tid;
        float4 s = make_float4(0.f, 0.f, 0.f, 0.f);
#pragma unroll
        for (int j = 0; j < SPLITK; j++) {
            float4 t = ((const float4*)(g_part + (size_t)j * 32 * QKV_N + (size_t)b * QKV_N))[i4];
            s.x += t.x; s.y += t.y; s.z += t.z; s.w += t.w;
        }
        ((float4*)sq)[tid] = s;
    }
    if (tid < 64) {
        const double LOG_THETA_OVER_HALF = 0.20503692777194265;  // ln(500000)/64
        double inv = exp(-(double)tid * LOG_THETA_OVER_HALF);
        double f = (double)pos * inv;
        double sd, cd;
        sincos(f, &sd, &cd);
        scs[tid] = (float)cd; ssn[tid] = (float)sd;
    }
    __syncthreads();

    float* out = g_qkv + (size_t)b * QKV_N + cbase;
#pragma unroll
    for (int r = 0; r < 2; r++) {
        int p = tid + r * 128;
        int h = p >> 6, d = p & 63;
        int c1 = h * 128 + d, c2 = c1 + 64;
        float x1 = sq[c1], x2 = sq[c2];
        float cs = scs[d], sn = ssn[d];
        out[c1] = x1 * cs - x2 * sn;
        out[c2] = x2 * cs + x1 * sn;
    }
}

// ------------------------- split-K sum, v passthrough ------------------------
// grid: 64 = 32 b x 2 groups. block 128.
__global__ void __launch_bounds__(128) rope_v_kernel() {
    int blk = blockIdx.x;
    int grp = blk & 1;
    int b   = blk >> 1;
    int tid = threadIdx.x;
    int i4 = (5120 + grp * 512) / 4 + tid;
    float4 s = make_float4(0.f, 0.f, 0.f, 0.f);
#pragma unroll
    for (int j = 0; j < SPLITK; j++) {
        float4 t = ((const float4*)(g_part + (size_t)j * 32 * QKV_N + (size_t)b * QKV_N))[i4];
        s.x += t.x; s.y += t.y; s.z += t.z; s.w += t.w;
    }
    ((float4*)(g_qkv + (size_t)b * QKV_N))[i4] = s;
}

// ------------------------- attention partial (flash-decode) -----------------
// grid: B*NKV*NCHUNK = 4096, block 256 (8 warps, warp-per-key-pair).
__global__ void __launch_bounds__(256, 3) attn_partial_kernel(
    const float* __restrict__ kc, const float* __restrict__ vc,
    const int* __restrict__ positions, const int* __restrict__ bt)
{
    int x = blockIdx.x;
    int c  = x & (NCHUNK - 1);
    int kv = (x >> 4) & 7;
    int b  = x >> 7;
    int tid = threadIdx.x;
    int pos = positions[b];
    int L = pos + 1;
    int s0 = c * CHUNK;
    if (s0 >= L) return;                 // empty chunk: combine skips it
    int s1 = min(s0 + CHUNK, L);
    int sEnd = min(s1, pos);             // cache keys strictly below pos
    bool hasNew = (pos < s1);            // this chunk owns the new token

    float* pbase = g_attn_part + (size_t)x * PART_STRIDE;

    __shared__ int sbt[8];               // block-table slice for 128-key chunk
    if (tid < 8) sbt[tid] = bt[b * MAXB_ + (s0 >> 4) + tid];
    __syncthreads();

    int w = tid >> 5, lane = tid & 31;
    bool b1 = (lane & 1), b2 = (lane & 2), b4 = (lane & 4);
    const float4* qp = (const float4*)(g_qkv + (size_t)b * QKV_N + kv * 512);
    const float SCALE = 0.08838834764831845f;   // 1/sqrt(128)
    float4 q[4];
#pragma unroll
    for (int g = 0; g < 4; g++) {
        float4 t = qp[g * 32 + lane];
        q[g] = make_float4(t.x * SCALE, t.y * SCALE, t.z * SCALE, t.w * SCALE);
    }
    const float4* knew = (const float4*)(g_qkv + (size_t)b * QKV_N + 4096 + kv * 128);
    const float4* vnew = (const float4*)(g_qkv + (size_t)b * QKV_N + 5120 + kv * 128);

    const float* kcb = kc + (size_t)kv * 128 + lane * 4;
    const float* vcb = vc + (size_t)kv * 128 + lane * 4;

    float l1 = 0.f;
    float4 acc[4];
#pragma unroll
    for (int g = 0; g < 4; g++) acc[g] = make_float4(0.f, 0.f, 0.f, 0.f);

#define LOADQ(I, SX) do { int _s = (SX);                                   \
        if (_s < sEnd) {                                                   \
            int _slot = sbt[(_s - s0) >> 4] * 16 + (_s & 15);              \
            const float* _kp = kcb + ((size_t)_slot << 10);                \
            const float* _vp = vcb + ((size_t)_slot << 10);                \
            asm volatile("ld.global.cg.v4.f32 {%0,%1,%2,%3}, [%4];"        \
                : "=f"(kq[I].x), "=f"(kq[I].y), "=f"(kq[I].z), "=f"(kq[I].w) \
                : "l"(_kp));                                               \
            asm volatile("ld.global.cg.v4.f32 {%0,%1,%2,%3}, [%4];"        \
                : "=f"(vq[I].x), "=f"(vq[I].y), "=f"(vq[I].z), "=f"(vq[I].w) \
                : "l"(_vp));                                               \
        } } while (0)

#define STEP2(kkA, vvA, kkB, vvB, useB) do {                               \
        float a0 = fmaf(q[0].x, kkA.x, fmaf(q[0].y, kkA.y, fmaf(q[0].z, kkA.z, q[0].w * kkA.w))); \
        float a1 = fmaf(q[1].x, kkA.x, fmaf(q[1].y, kkA.y, fmaf(q[1].z, kkA.z, q[1].w * kkA.w))); \
        float a2 = fmaf(q[2].x, kkA.x, fmaf(q[2].y, kkA.y, fmaf(q[2].z, kkA.z, q[2].w * kkA.w))); \
        float a3 = fmaf(q[3].x, kkA.x, fmaf(q[3].y, kkA.y, fmaf(q[3].z, kkA.z, q[3].w * kkA.w))); \
        float c0 = fmaf(q[0].x, kkB.x, fmaf(q[0].y, kkB.y, fmaf(q[0].z, kkB.z, q[0].w * kkB.w))); \
        float c1 = fmaf(q[1].x, kkB.x, fmaf(q[1].y, kkB.y, fmaf(q[1].z, kkB.z, q[1].w * kkB.w))); \
        float c2 = fmaf(q[2].x, kkB.x, fmaf(q[2].y, kkB.y, fmaf(q[2].z, kkB.z, q[2].w * kkB.w))); \
        float c3 = fmaf(q[3].x, kkB.x, fmaf(q[3].y, kkB.y, fmaf(q[3].z, kkB.z, q[3].w * kkB.w))); \
        float vA01 = (b1 ? a1 : a0) + __shfl_xor_sync(0xffffffffu, b1 ? a0 : a1, 1); \
        float vA23 = (b1 ? a3 : a2) + __shfl_xor_sync(0xffffffffu, b1 ? a2 : a3, 1); \
        float vB01 = (b1 ? c1 : c0) + __shfl_xor_sync(0xffffffffu, b1 ? c0 : c1, 1); \
        float vB23 = (b1 ? c3 : c2) + __shfl_xor_sync(0xffffffffu, b1 ? c2 : c3, 1); \
        float vA = (b2 ? vA23 : vA01) + __shfl_xor_sync(0xffffffffu, b2 ? vA01 : vA23, 2); \
        float vB = (b2 ? vB23 : vB01) + __shfl_xor_sync(0xffffffffu, b2 ? vB01 : vB23, 2); \
        float vv_ = (b4 ? vB : vA) + __shfl_xor_sync(0xffffffffu, b4 ? vA : vB, 4); \
        vv_ += __shfl_xor_sync(0xffffffffu, vv_, 8);                       \
        vv_ += __shfl_xor_sync(0xffffffffu, vv_, 16);                      \
        float px = __expf(vv_);                                            \
        if (b4 && !(useB)) px = 0.f;                                       \
        l1 += px;                                                          \
        float pA0 = __shfl_sync(0xffffffffu, px, 0, 8);                    \
        float pA1 = __shfl_sync(0xffffffffu, px, 1, 8);                    \
        float pA2 = __shfl_sync(0xffffffffu, px, 2, 8);                    \
        float pA3 = __shfl_sync(0xffffffffu, px, 3, 8);                    \
        float pB0 = __shfl_sync(0xffffffffu, px, 4, 8);                    \
        float pB1 = __shfl_sync(0xffffffffu, px, 5, 8);                    \
        float pB2 = __shfl_sync(0xffffffffu, px, 6, 8);                    \
        float pB3 = __shfl_sync(0xffffffffu, px, 7, 8);                    \
        acc[0].x = fmaf(pA0, vvA.x, fmaf(pB0, vvB.x, acc[0].x));           \
        acc[0].y = fmaf(pA0, vvA.y, fmaf(pB0, vvB.y, acc[0].y));           \
        acc[0].z = fmaf(pA0, vvA.z, fmaf(pB0, vvB.z, acc[0].z));           \
        acc[0].w = fmaf(pA0, vvA.w, fmaf(pB0, vvB.w, acc[0].w));           \
        acc[1].x = fmaf(pA1, vvA.x, fmaf(pB1, vvB.x, acc[1].x));           \
        acc[1].y = fmaf(pA1, vvA.y, fmaf(pB1, vvB.y, acc[1].y));           \
        acc[1].z = fmaf(pA1, vvA.z, fmaf(pB1, vvB.z, acc[1].z));           \
        acc[1].w = fmaf(pA1, vvA.w, fmaf(pB1, vvB.w, acc[1].w));           \
        acc[2].x = fmaf(pA2, vvA.x, fmaf(pB2, vvB.x, acc[2].x));           \
        acc[2].y = fmaf(pA2, vvA.y, fmaf(pB2, vvB.y, acc[2].y));           \
        acc[2].z = fmaf(pA2, vvA.z, fmaf(pB2, vvB.z, acc[2].z));           \
        acc[2].w = fmaf(pA2, vvA.w, fmaf(pB2, vvB.w, acc[2].w));           \
        acc[3].x = fmaf(pA3, vvA.x, fmaf(pB3, vvB.x, acc[3].x));           \
        acc[3].y = fmaf(pA3, vvA.y, fmaf(pB3, vvB.y, acc[3].y));           \
        acc[3].z = fmaf(pA3, vvA.z, fmaf(pB3, vvB.z, acc[3].z));           \
        acc[3].w = fmaf(pA3, vvA.w, fmaf(pB3, vvB.w, acc[3].w));           \
    } while (0)

    float4 kq[2], vq[2];
#pragma unroll
    for (int i = 0; i < 2; i++) { kq[i] = make_float4(0,0,0,0); vq[i] = kq[i]; }
    int s = s0 + w;
    LOADQ(0, s); LOADQ(1, s + 8);

    for (; s < sEnd; s += 16) {
        float4 kkA = kq[0], vvA = vq[0], kkB = kq[1], vvB = vq[1];
        bool useB = (s + 8 < sEnd);      // warp-uniform
        LOADQ(0, s + 16); LOADQ(1, s + 24);
        STEP2(kkA, vvA, kkB, vvB, useB);
    }

    if (hasNew && w == 0) {
        float4 kk = knew[lane], vv = vnew[lane];
        float4 zz = make_float4(0.f, 0.f, 0.f, 0.f);
        STEP2(kk, vv, zz, zz, false);
    }
#undef LOADQ
#undef STEP2

    l1 += __shfl_xor_sync(0xffffffffu, l1, 4);

    __shared__ float sm_l[8][4];
    __shared__ float4 sm_acc[8][4][32];
    if (lane < 4) sm_l[w][lane] = l1;
#pragma unroll
    for (int g = 0; g < 4; g++) sm_acc[w][g][lane] = acc[g];
    __syncthreads();

    if (tid < 128) {
        int g = tid >> 5;
        int ln = tid & 31;
        float ll = 0.f;
        float4 aa = make_float4(0.f, 0.f, 0.f, 0.f);
#pragma unroll
        for (int ww = 0; ww < 8; ww++) {
            ll += sm_l[ww][g];
            float4 t = sm_acc[ww][g][ln];
            aa.x += t.x; aa.y += t.y; aa.z += t.z; aa.w += t.w;
        }
        if (ln == 0) pbase[4 + g] = ll;
        ((float4*)(pbase + 8))[g * 32 + ln] = aa;
    }
}

// ------------------------- attention combine --------------------------------
// grid: B*NKV = 256, block 128. Plain sum of active chunks (fixed reference).
__global__ void __launch_bounds__(128) attn_combine_kernel(const int* __restrict__ positions) {
    int x = blockIdx.x;                 // b*8 + kv
    int b = x >> 3;
    int L = positions[b] + 1;
    int nc = min(NCHUNK, (L + CHUNK - 1) / CHUNK);
    int g = threadIdx.x >> 5;
    int ln = threadIdx.x & 31;
    const float* base0 = g_attn_part + (size_t)x * NCHUNK * PART_STRIDE;

    float ll = 0.f;
    float4 aa = make_float4(0.f, 0.f, 0.f, 0.f);
#pragma unroll
    for (int hw = 0; hw < 2; hw++) {
        float lv[8];
        float4 tv[8];
#pragma unroll
        for (int j = 0; j < 8; j++) {
            int c = hw * 8 + j;
            const float* base = base0 + (size_t)c * PART_STRIDE;
            if (c < nc) {
                lv[j] = base[4 + g];
                tv[j] = ((const float4*)(base + 8))[g * 32 + ln];
            } else {
                lv[j] = 0.f; tv[j] = make_float4(0.f, 0.f, 0.f, 0.f);
            }
        }
#pragma unroll
        for (int j = 0; j < 8; j++) {
            ll += lv[j];
            aa.x += tv[j].x; aa.y += tv[j].y; aa.z += tv[j].z; aa.w += tv[j].w;
        }
    }
    float inv = 1.f / ll;
    ((float4*)g_attn_out)[(size_t)x * 128 + g * 32 + ln] =
        make_float4(aa.x * inv, aa.y * inv, aa.z * inv, aa.w * inv);
}

// ------------------------- final split-K reduce ------------------------------
__global__ void __launch_bounds__(256) add_out_kernel(float* __restrict__ out) {
    int i = blockIdx.x * 256 + threadIdx.x;       // float4 index, 32768 total
    float4 s = make_float4(0.f, 0.f, 0.f, 0.f);
#pragma unroll
    for (int j = 0; j < SPLITK; j++) {
        float4 t = ((const float4*)g_part)[(size_t)j * (B_ * HID_ / 4) + i];
        s.x += t.x; s.y += t.y; s.z += t.z; s.w += t.w;
    }
    ((float4*)out)[i] = s;
}

// ------------------------- launch ------------------------------------------
extern "C" void kernel_launch(void* const* d_in, const int* in_sizes, int n_in,
                              void* d_out, int out_size) {
    const float* hidden = 0; const float* w_qkv = 0; const float* w_o = 0;
    const float* k_cache = 0; const float* v_cache = 0;
    const int* positions = 0; const int* btables = 0;
    for (int i = 0; i < n_in; i++) {
        int sz = in_sizes[i];
        if (sz == B_ * HID_)               hidden  = (const float*)d_in[i];
        else if (sz == HID_ * QKV_N)       w_qkv   = (const float*)d_in[i];
        else if (sz == NH_ * HD_ * HID_)   w_o     = (const float*)d_in[i];
        else if (sz == 4096 * BS_ * NKV_ * HD_) {
            if (!k_cache) k_cache = (const float*)d_in[i];
            else if (!v_cache) v_cache = (const float*)d_in[i];
        }
        else if (sz == B_) { if (!positions) positions = (const int*)d_in[i]; }
        else if (sz == B_ * MAXB_)         btables = (const int*)d_in[i];
    }
    float* out = (float*)d_out;

    // two no-ops so the ncu capture window (launch #4) lands on gemm1
    noop_kernel<<<1, 32>>>();
    noop_kernel<<<1, 32>>>();
    // 1. qkv = hidden @ w_qkv  (3xTF32 mma, split-K=16, per-warp cp.async ring)
    prep_frag_kernel<<<512, 256>>>(hidden);
    gemm_mma3_kernel<<<dim3(QKV_N / GNT, SPLITK), 128>>>(w_qkv, QKV_N);
    // 2. combine + RoPE
    rope_qk_kernel<<<B_ * 10, 128>>>(positions);
    rope_v_kernel<<<B_ * 2, 128>>>();
    // 3. paged attention (flash-decode partials + combine)
    attn_partial_kernel<<<B_ * NKV_ * NCHUNK, 256>>>(k_cache, v_cache, positions, btables);
    attn_combine_kernel<<<B_ * NKV_, 128>>>(positions);
    // 4. out = attn @ w_o
    prep_frag_attn_kernel<<<512, 256>>>();
    gemm_mma3_kernel<<<dim3(HID_ / GNT, SPLITK), 128>>>(w_o, HID_);
    add_out_kernel<<<B_ * HID_ / 4 / 256, 256>>>(out);
}

// round 16
// speedup vs baseline: 1.1962x; 1.1817x over previous
#include <cuda_runtime.h>
#include <cuda_fp16.h>
#include <math.h>

#define B_    32
#define HID_  4096
#define NH_   32
#define NKV_  8
#define HD_   128
#define BS_   16
#define MAXB_ 128
#define S_    2048
#define QKV_N 6144
#define NCHUNK 16
#define CHUNK 128
#define PART_STRIDE 528

#define SPLITK 16
#define GSLICE 256           // K rows per split slice
#define GK16   16            // k16 steps per slice
#define GNT    128           // N cols per GEMM block (4 warps x n32)
#define WROW   36            // smem row stride (floats) -> conflict-free fp16 frag reads
#define WSTG   (16 * WROW)
#define WREG   (4 * WSTG)

// ------------------------- scratch (device globals) -------------------------
// Referenced ONLY inside device code (host-side symbol decay = round-0 bug).
__device__ __align__(16) unsigned g_fAh[65536];   // fp16x2 A fragments (hi)
__device__ __align__(16) unsigned g_fAl[65536];   // fp16x2 A fragments (lo, unscaled)
__device__ __align__(16) float g_part[SPLITK * B_ * QKV_N];
__device__ __align__(16) float g_qkv[B_ * QKV_N];
__device__ __align__(16) float g_attn_part[B_ * NKV_ * NCHUNK * PART_STRIDE];
__device__ __align__(16) float g_attn_out[B_ * NH_ * HD_];

// ------------------------- helpers ------------------------------------------
__device__ __forceinline__ unsigned packh2(float hi, float lo) {
    unsigned d;
    asm("cvt.rn.f16x2.f32 %0, %1, %2;" : "=r"(d) : "f"(hi), "f"(lo));
    return d;
}

__device__ __forceinline__ void mma16(float acc[4], unsigned a0, unsigned a1,
                                      unsigned a2, unsigned a3,
                                      unsigned b0, unsigned b1) {
    asm volatile(
        "mma.sync.aligned.m16n8k16.row.col.f32.f16.f16.f32 "
        "{%0,%1,%2,%3},{%4,%5,%6,%7},{%8,%9},{%0,%1,%2,%3};"
        : "+f"(acc[0]), "+f"(acc[1]), "+f"(acc[2]), "+f"(acc[3])
        : "r"(a0), "r"(a1), "r"(a2), "r"(a3), "r"(b0), "r"(b1));
}

__global__ void noop_kernel() {}   // shifts ncu window: launch #4 = gemm1

// ------------------------- A-fragment prep (m16n8k16 fp16 layout) -----------
// frag reg j of (k16,mt,lane): row = mt*16+(lane>>2)+(j&1)*8,
// cols = k16*16+(lane&3)*2+(j>>1)*8 +{0,1}. uint idx = ((k16*2+mt)*32+lane)*4+j.
__device__ __forceinline__ void prep16_body(const float* A, int idx) {
    int j    = idx & 3;
    int lane = (idx >> 2) & 31;
    int mt   = (idx >> 7) & 1;
    int k16  = idx >> 8;
    int row = mt * 16 + (lane >> 2) + (j & 1) * 8;
    int col = k16 * 16 + (lane & 3) * 2 + (j >> 1) * 8;
    float v0 = A[row * HID_ + col];
    float v1 = A[row * HID_ + col + 1];
    __half h0 = __float2half_rn(v0), h1 = __float2half_rn(v1);
    float l0 = v0 - __half2float(h0);
    float l1 = v1 - __half2float(h1);
    g_fAh[idx] = packh2(v1 * 0.f + __half2float(h1), __half2float(h0)); // exact h1,h0
    g_fAl[idx] = packh2(l1, l0);
}
__global__ void __launch_bounds__(256) prep16_kernel(const float* __restrict__ A) {
    prep16_body(A, blockIdx.x * 256 + threadIdx.x);
}
__global__ void __launch_bounds__(256) prep16_attn_kernel() {
    prep16_body(g_attn_out, blockIdx.x * 256 + threadIdx.x);
}

// ------------------------- 3xFP16 tensor-core GEMM --------------------------
// C[32,N] = A[32,4096] @ W[4096,N].  grid (N/GNT, SPLITK), block 128 (4 warps).
// Per-warp private cp.async ring (no block barriers). One k16 per chunk.
// Passes: accH += Ah*Wh; accH += Al*Wh; accH += (Ah*2^-5)*(Wl*32).
__global__ void __launch_bounds__(128, 4) gemm_fp16_kernel(
    const float* __restrict__ W, int N)
{
    __shared__ float sW[4 * WREG];        // 36 KB
    int tid = threadIdx.x;
    int w = tid >> 5, lane = tid & 31;
    int nb = blockIdx.x, kb = blockIdx.y;
    int n0 = nb * GNT;
    int k0 = kb * GSLICE;
    int k16base = k0 >> 4;

    unsigned sbase;
    asm("{ .reg .u64 t; cvta.to.shared.u64 t, %1; cvt.u32.u64 %0, t; }"
        : "=r"(sbase) : "l"(sW));
    unsigned wbase = sbase + (unsigned)(w * WREG) * 4u;
    const float* wsrc0 = W + (size_t)k0 * N + n0 + w * 32;

    int srow[4], sseg[4];
#pragma unroll
    for (int p = 0; p < 4; p++) {
        int f = p * 32 + lane;
        srow[p] = f >> 3;
        sseg[p] = f & 7;
    }

#define STAGE(C) do { int _c = (C);                                          \
        unsigned _sb = wbase + (unsigned)((_c & 3) * WSTG) * 4u;              \
        const float* _src = wsrc0 + (size_t)(_c * 16) * N;                    \
        _Pragma("unroll")                                                     \
        for (int _p = 0; _p < 4; _p++) {                                      \
            unsigned _dst = _sb + (unsigned)(srow[_p] * WROW + sseg[_p] * 4) * 4u; \
            const float* _g = _src + (size_t)srow[_p] * N + sseg[_p] * 4;     \
            asm volatile("cp.async.cg.shared.global [%0], [%1], 16;"          \
                         :: "r"(_dst), "l"(_g));                              \
        }                                                                     \
        asm volatile("cp.async.commit_group;"); } while (0)

    float acc[2][4][4];
#pragma unroll
    for (int mf = 0; mf < 2; mf++)
#pragma unroll
        for (int nf = 0; nf < 4; nf++)
#pragma unroll
            for (int i = 0; i < 4; i++) acc[mf][nf][i] = 0.f;

    const uint4* fah = (const uint4*)g_fAh;
    const uint4* fal = (const uint4*)g_fAl;

    uint4 nah0 = __ldg(&fah[(size_t)(k16base * 2 + 0) * 32 + lane]);
    uint4 nah1 = __ldg(&fah[(size_t)(k16base * 2 + 1) * 32 + lane]);
    uint4 nal0 = __ldg(&fal[(size_t)(k16base * 2 + 0) * 32 + lane]);
    uint4 nal1 = __ldg(&fal[(size_t)(k16base * 2 + 1) * 32 + lane]);

    STAGE(0); STAGE(1); STAGE(2);

    const float* swarp = sW + w * WREG;
    const unsigned SC5 = 0x28002800u;     // fp16x2 {2^-5, 2^-5}

    for (int kk = 0; kk < GK16; kk++) {
        int rem = GK16 - 1 - kk;
        if (rem >= 2)      asm volatile("cp.async.wait_group 2;" ::: "memory");
        else if (rem == 1) asm volatile("cp.async.wait_group 1;" ::: "memory");
        else               asm volatile("cp.async.wait_group 0;" ::: "memory");
        __syncwarp();
        if (kk + 3 < GK16) STAGE(kk + 3);

        uint4 ah0 = nah0, ah1 = nah1, al0 = nal0, al1 = nal1;
        if (kk < GK16 - 1) {
            int kn = k16base + kk + 1;
            nah0 = __ldg(&fah[(size_t)(kn * 2 + 0) * 32 + lane]);
            nah1 = __ldg(&fah[(size_t)(kn * 2 + 1) * 32 + lane]);
            nal0 = __ldg(&fal[(size_t)(kn * 2 + 0) * 32 + lane]);
            nal1 = __ldg(&fal[(size_t)(kn * 2 + 1) * 32 + lane]);
        }

        // Ah * 2^-5 (exponent-exact) for the W-residual pass
        uint4 as0, as1;
        asm("mul.f16x2 %0, %1, %2;" : "=r"(as0.x) : "r"(ah0.x), "r"(SC5));
        asm("mul.f16x2 %0, %1, %2;" : "=r"(as0.y) : "r"(ah0.y), "r"(SC5));
        asm("mul.f16x2 %0, %1, %2;" : "=r"(as0.z) : "r"(ah0.z), "r"(SC5));
        asm("mul.f16x2 %0, %1, %2;" : "=r"(as0.w) : "r"(ah0.w), "r"(SC5));
        asm("mul.f16x2 %0, %1, %2;" : "=r"(as1.x) : "r"(ah1.x), "r"(SC5));
        asm("mul.f16x2 %0, %1, %2;" : "=r"(as1.y) : "r"(ah1.y), "r"(SC5));
        asm("mul.f16x2 %0, %1, %2;" : "=r"(as1.z) : "r"(ah1.z), "r"(SC5));
        asm("mul.f16x2 %0, %1, %2;" : "=r"(as1.w) : "r"(ah1.w), "r"(SC5));

        const float* sb0 = swarp + (kk & 3) * WSTG;
        int r0 = (lane & 3) * 2;
        int cc = (lane >> 2);

        unsigned bh0[4], bh1[4], bl0[4], bl1[4];
#pragma unroll
        for (int nf = 0; nf < 4; nf++) {
            const float* p = sb0 + r0 * WROW + cc + nf * 8;
            float v0 = p[0];
            float v1 = p[WROW];
            float v8 = p[8 * WROW];
            float v9 = p[9 * WROW];
            bh0[nf] = packh2(v1, v0);
            bh1[nf] = packh2(v9, v8);
            __half2 H0 = *reinterpret_cast<__half2*>(&bh0[nf]);
            __half2 H1 = *reinterpret_cast<__half2*>(&bh1[nf]);
            bl0[nf] = packh2((v1 - __high2float(H0)) * 32.f,
                             (v0 - __low2float(H0))  * 32.f);
            bl1[nf] = packh2((v9 - __high2float(H1)) * 32.f,
                             (v8 - __low2float(H1))  * 32.f);
        }
        // pass 1: Ah x Wh (8 independent accumulators)
#pragma unroll
        for (int nf = 0; nf < 4; nf++)
            mma16(acc[0][nf], ah0.x, ah0.y, ah0.z, ah0.w, bh0[nf], bh1[nf]);
#pragma unroll
        for (int nf = 0; nf < 4; nf++)
            mma16(acc[1][nf], ah1.x, ah1.y, ah1.z, ah1.w, bh0[nf], bh1[nf]);
        // pass 2: Al x Wh
#pragma unroll
        for (int nf = 0; nf < 4; nf++)
            mma16(acc[0][nf], al0.x, al0.y, al0.z, al0.w, bh0[nf], bh1[nf]);
#pragma unroll
        for (int nf = 0; nf < 4; nf++)
            mma16(acc[1][nf], al1.x, al1.y, al1.z, al1.w, bh0[nf], bh1[nf]);
        // pass 3: (Ah/32) x (Wl*32)
#pragma unroll
        for (int nf = 0; nf < 4; nf++)
            mma16(acc[0][nf], as0.x, as0.y, as0.z, as0.w, bl0[nf], bl1[nf]);
#pragma unroll
        for (int nf = 0; nf < 4; nf++)
            mma16(acc[1][nf], as1.x, as1.y, as1.z, as1.w, bl0[nf], bl1[nf]);
    }
#undef STAGE

    float* op = g_part + (size_t)kb * 32 * N + n0 + w * 32;
    int r = lane >> 2, c2 = (lane & 3) * 2;
#pragma unroll
    for (int mf = 0; mf < 2; mf++)
#pragma unroll
        for (int nf = 0; nf < 4; nf++) {
            *(float2*)(op + (size_t)(mf * 16 + r    ) * N + nf * 8 + c2) =
                make_float2(acc[mf][nf][0], acc[mf][nf][1]);
            *(float2*)(op + (size_t)(mf * 16 + r + 8) * N + nf * 8 + c2) =
                make_float2(acc[mf][nf][2], acc[mf][nf][3]);
        }
}

// ------------------------- split-K sum + RoPE (q,k heads) -------------------
__global__ void __launch_bounds__(128) rope_qk_kernel(const int* __restrict__ positions) {
    __shared__ float sq[512];
    __shared__ float scs[64], ssn[64];
    int blk = blockIdx.x;
    int grp = blk % 10;
    int b   = blk / 10;
    int tid = threadIdx.x;
    int pos = positions[b];
    int cbase = grp * 512;
    {
        int i4 = cbase / 4 + tid;
        float4 s = make_float4(0.f, 0.f, 0.f, 0.f);
#pragma unroll
        for (int j = 0; j < SPLITK; j++) {
            float4 t = ((const float4*)(g_part + (size_t)j * 32 * QKV_N + (size_t)b * QKV_N))[i4];
            s.x += t.x; s.y += t.y; s.z += t.z; s.w += t.w;
        }
        ((float4*)sq)[tid] = s;
    }
    if (tid < 64) {
        const double LOG_THETA_OVER_HALF = 0.20503692777194265;  // ln(500000)/64
        double inv = exp(-(double)tid * LOG_THETA_OVER_HALF);
        double f = (double)pos * inv;
        double sd, cd;
        sincos(f, &sd, &cd);
        scs[tid] = (float)cd; ssn[tid] = (float)sd;
    }
    __syncthreads();
    float* out = g_qkv + (size_t)b * QKV_N + cbase;
#pragma unroll
    for (int r = 0; r < 2; r++) {
        int p = tid + r * 128;
        int h = p >> 6, d = p & 63;
        int c1 = h * 128 + d, c2 = c1 + 64;
        float x1 = sq[c1], x2 = sq[c2];
        float cs = scs[d], sn = ssn[d];
        out[c1] = x1 * cs - x2 * sn;
        out[c2] = x2 * cs + x1 * sn;
    }
}

__global__ void __launch_bounds__(128) rope_v_kernel() {
    int blk = blockIdx.x;
    int grp = blk & 1;
    int b   = blk >> 1;
    int tid = threadIdx.x;
    int i4 = (5120 + grp * 512) / 4 + tid;
    float4 s = make_float4(0.f, 0.f, 0.f, 0.f);
#pragma unroll
    for (int j = 0; j < SPLITK; j++) {
        float4 t = ((const float4*)(g_part + (size_t)j * 32 * QKV_N + (size_t)b * QKV_N))[i4];
        s.x += t.x; s.y += t.y; s.z += t.z; s.w += t.w;
    }
    ((float4*)(g_qkv + (size_t)b * QKV_N))[i4] = s;
}

// ------------------------- attention partial (flash-decode, best build) -----
__global__ void __launch_bounds__(256, 3) attn_partial_kernel(
    const float* __restrict__ kc, const float* __restrict__ vc,
    const int* __restrict__ positions, const int* __restrict__ bt)
{
    int x = blockIdx.x;
    int c  = x & (NCHUNK - 1);
    int kv = (x >> 4) & 7;
    int b  = x >> 7;
    int tid = threadIdx.x;
    int pos = positions[b];
    int L = pos + 1;
    int s0 = c * CHUNK;
    if (s0 >= L) return;
    int s1 = min(s0 + CHUNK, L);
    int sEnd = min(s1, pos);
    bool hasNew = (pos < s1);

    float* pbase = g_attn_part + (size_t)x * PART_STRIDE;

    __shared__ int sbt[8];
    if (tid < 8) sbt[tid] = bt[b * MAXB_ + (s0 >> 4) + tid];
    __syncthreads();

    int w = tid >> 5, lane = tid & 31;
    bool b1 = (lane & 1), b2 = (lane & 2), b4 = (lane & 4);
    const float4* qp = (const float4*)(g_qkv + (size_t)b * QKV_N + kv * 512);
    const float SCALE = 0.08838834764831845f;
    float4 q[4];
#pragma unroll
    for (int g = 0; g < 4; g++) {
        float4 t = qp[g * 32 + lane];
        q[g] = make_float4(t.x * SCALE, t.y * SCALE, t.z * SCALE, t.w * SCALE);
    }
    const float4* knew = (const float4*)(g_qkv + (size_t)b * QKV_N + 4096 + kv * 128);
    const float4* vnew = (const float4*)(g_qkv + (size_t)b * QKV_N + 5120 + kv * 128);

    const float* kcb = kc + (size_t)kv * 128 + lane * 4;
    const float* vcb = vc + (size_t)kv * 128 + lane * 4;

    float l1 = 0.f;
    float4 acc[4];
#pragma unroll
    for (int g = 0; g < 4; g++) acc[g] = make_float4(0.f, 0.f, 0.f, 0.f);

#define LOADQ(I, SX) do { int _s = (SX);                                   \
        if (_s < sEnd) {                                                   \
            int _slot = sbt[(_s - s0) >> 4] * 16 + (_s & 15);              \
            const float* _kp = kcb + ((size_t)_slot << 10);                \
            const float* _vp = vcb + ((size_t)_slot << 10);                \
            asm volatile("ld.global.cg.v4.f32 {%0,%1,%2,%3}, [%4];"        \
                : "=f"(kq[I].x), "=f"(kq[I].y), "=f"(kq[I].z), "=f"(kq[I].w) \
                : "l"(_kp));                                               \
            asm volatile("ld.global.cg.v4.f32 {%0,%1,%2,%3}, [%4];"        \
                : "=f"(vq[I].x), "=f"(vq[I].y), "=f"(vq[I].z), "=f"(vq[I].w) \
                : "l"(_vp));                                               \
        } } while (0)

#define STEP2(kkA, vvA, kkB, vvB, useB) do {                               \
        float a0 = fmaf(q[0].x, kkA.x, fmaf(q[0].y, kkA.y, fmaf(q[0].z, kkA.z, q[0].w * kkA.w))); \
        float a1 = fmaf(q[1].x, kkA.x, fmaf(q[1].y, kkA.y, fmaf(q[1].z, kkA.z, q[1].w * kkA.w))); \
        float a2 = fmaf(q[2].x, kkA.x, fmaf(q[2].y, kkA.y, fmaf(q[2].z, kkA.z, q[2].w * kkA.w))); \
        float a3 = fmaf(q[3].x, kkA.x, fmaf(q[3].y, kkA.y, fmaf(q[3].z, kkA.z, q[3].w * kkA.w))); \
        float c0 = fmaf(q[0].x, kkB.x, fmaf(q[0].y, kkB.y, fmaf(q[0].z, kkB.z, q[0].w * kkB.w))); \
        float c1 = fmaf(q[1].x, kkB.x, fmaf(q[1].y, kkB.y, fmaf(q[1].z, kkB.z, q[1].w * kkB.w))); \
        float c2 = fmaf(q[2].x, kkB.x, fmaf(q[2].y, kkB.y, fmaf(q[2].z, kkB.z, q[2].w * kkB.w))); \
        float c3 = fmaf(q[3].x, kkB.x, fmaf(q[3].y, kkB.y, fmaf(q[3].z, kkB.z, q[3].w * kkB.w))); \
        float vA01 = (b1 ? a1 : a0) + __shfl_xor_sync(0xffffffffu, b1 ? a0 : a1, 1); \
        float vA23 = (b1 ? a3 : a2) + __shfl_xor_sync(0xffffffffu, b1 ? a2 : a3, 1); \
        float vB01 = (b1 ? c1 : c0) + __shfl_xor_sync(0xffffffffu, b1 ? c0 : c1, 1); \
        float vB23 = (b1 ? c3 : c2) + __shfl_xor_sync(0xffffffffu, b1 ? c2 : c3, 1); \
        float vA = (b2 ? vA23 : vA01) + __shfl_xor_sync(0xffffffffu, b2 ? vA01 : vA23, 2); \
        float vB = (b2 ? vB23 : vB01) + __shfl_xor_sync(0xffffffffu, b2 ? vB01 : vB23, 2); \
        float vv_ = (b4 ? vB : vA) + __shfl_xor_sync(0xffffffffu, b4 ? vA : vB, 4); \
        vv_ += __shfl_xor_sync(0xffffffffu, vv_, 8);                       \
        vv_ += __shfl_xor_sync(0xffffffffu, vv_, 16);                      \
        float px = __expf(vv_);                                            \
        if (b4 && !(useB)) px = 0.f;                                       \
        l1 += px;                                                          \
        float pA0 = __shfl_sync(0xffffffffu, px, 0, 8);                    \
        float pA1 = __shfl_sync(0xffffffffu, px, 1, 8);                    \
        float pA2 = __shfl_sync(0xffffffffu, px, 2, 8);                    \
        float pA3 = __shfl_sync(0xffffffffu, px, 3, 8);                    \
        float pB0 = __shfl_sync(0xffffffffu, px, 4, 8);                    \
        float pB1 = __shfl_sync(0xffffffffu, px, 5, 8);                    \
        float pB2 = __shfl_sync(0xffffffffu, px, 6, 8);                    \
        float pB3 = __shfl_sync(0xffffffffu, px, 7, 8);                    \
        acc[0].x = fmaf(pA0, vvA.x, fmaf(pB0, vvB.x, acc[0].x));           \
        acc[0].y = fmaf(pA0, vvA.y, fmaf(pB0, vvB.y, acc[0].y));           \
        acc[0].z = fmaf(pA0, vvA.z, fmaf(pB0, vvB.z, acc[0].z));           \
        acc[0].w = fmaf(pA0, vvA.w, fmaf(pB0, vvB.w, acc[0].w));           \
        acc[1].x = fmaf(pA1, vvA.x, fmaf(pB1, vvB.x, acc[1].x));           \
        acc[1].y = fmaf(pA1, vvA.y, fmaf(pB1, vvB.y, acc[1].y));           \
        acc[1].z = fmaf(pA1, vvA.z, fmaf(pB1, vvB.z, acc[1].z));           \
        acc[1].w = fmaf(pA1, vvA.w, fmaf(pB1, vvB.w, acc[1].w));           \
        acc[2].x = fmaf(pA2, vvA.x, fmaf(pB2, vvB.x, acc[2].x));           \
        acc[2].y = fmaf(pA2, vvA.y, fmaf(pB2, vvB.y, acc[2].y));           \
        acc[2].z = fmaf(pA2, vvA.z, fmaf(pB2, vvB.z, acc[2].z));           \
        acc[2].w = fmaf(pA2, vvA.w, fmaf(pB2, vvB.w, acc[2].w));           \
        acc[3].x = fmaf(pA3, vvA.x, fmaf(pB3, vvB.x, acc[3].x));           \
        acc[3].y = fmaf(pA3, vvA.y, fmaf(pB3, vvB.y, acc[3].y));           \
        acc[3].z = fmaf(pA3, vvA.z, fmaf(pB3, vvB.z, acc[3].z));           \
        acc[3].w = fmaf(pA3, vvA.w, fmaf(pB3, vvB.w, acc[3].w));           \
    } while (0)

    float4 kq[2], vq[2];
#pragma unroll
    for (int i = 0; i < 2; i++) { kq[i] = make_float4(0,0,0,0); vq[i] = kq[i]; }
    int s = s0 + w;
    LOADQ(0, s); LOADQ(1, s + 8);

    for (; s < sEnd; s += 16) {
        float4 kkA = kq[0], vvA = vq[0], kkB = kq[1], vvB = vq[1];
        bool useB = (s + 8 < sEnd);
        LOADQ(0, s + 16); LOADQ(1, s + 24);
        STEP2(kkA, vvA, kkB, vvB, useB);
    }

    if (hasNew && w == 0) {
        float4 kk = knew[lane], vv = vnew[lane];
        float4 zz = make_float4(0.f, 0.f, 0.f, 0.f);
        STEP2(kk, vv, zz, zz, false);
    }
#undef LOADQ
#undef STEP2

    l1 += __shfl_xor_sync(0xffffffffu, l1, 4);

    __shared__ float sm_l[8][4];
    __shared__ float4 sm_acc[8][4][32];
    if (lane < 4) sm_l[w][lane] = l1;
#pragma unroll
    for (int g = 0; g < 4; g++) sm_acc[w][g][lane] = acc[g];
    __syncthreads();

    if (tid < 128) {
        int g = tid >> 5;
        int ln = tid & 31;
        float ll = 0.f;
        float4 aa = make_float4(0.f, 0.f, 0.f, 0.f);
#pragma unroll
        for (int ww = 0; ww < 8; ww++) {
            ll += sm_l[ww][g];
            float4 t = sm_acc[ww][g][ln];
            aa.x += t.x; aa.y += t.y; aa.z += t.z; aa.w += t.w;
        }
        if (ln == 0) pbase[4 + g] = ll;
        ((float4*)(pbase + 8))[g * 32 + ln] = aa;
    }
}

// ------------------------- attention combine --------------------------------
__global__ void __launch_bounds__(128) attn_combine_kernel(const int* __restrict__ positions) {
    int x = blockIdx.x;
    int b = x >> 3;
    int L = positions[b] + 1;
    int nc = min(NCHUNK, (L + CHUNK - 1) / CHUNK);
    int g = threadIdx.x >> 5;
    int ln = threadIdx.x & 31;
    const float* base0 = g_attn_part + (size_t)x * NCHUNK * PART_STRIDE;

    float ll = 0.f;
    float4 aa = make_float4(0.f, 0.f, 0.f, 0.f);
#pragma unroll
    for (int hw = 0; hw < 2; hw++) {
        float lv[8];
        float4 tv[8];
#pragma unroll
        for (int j = 0; j < 8; j++) {
            int c = hw * 8 + j;
            const float* base = base0 + (size_t)c * PART_STRIDE;
            if (c < nc) {
                lv[j] = base[4 + g];
                tv[j] = ((const float4*)(base + 8))[g * 32 + ln];
            } else {
                lv[j] = 0.f; tv[j] = make_float4(0.f, 0.f, 0.f, 0.f);
            }
        }
#pragma unroll
        for (int j = 0; j < 8; j++) {
            ll += lv[j];
            aa.x += tv[j].x; aa.y += tv[j].y; aa.z += tv[j].z; aa.w += tv[j].w;
        }
    }
    float inv = 1.f / ll;
    ((float4*)g_attn_out)[(size_t)x * 128 + g * 32 + ln] =
        make_float4(aa.x * inv, aa.y * inv, aa.z * inv, aa.w * inv);
}

// ------------------------- final split-K reduce ------------------------------
__global__ void __launch_bounds__(256) add_out_kernel(float* __restrict__ out) {
    int i = blockIdx.x * 256 + threadIdx.x;
    float4 s = make_float4(0.f, 0.f, 0.f, 0.f);
#pragma unroll
    for (int j = 0; j < SPLITK; j++) {
        float4 t = ((const float4*)g_part)[(size_t)j * (B_ * HID_ / 4) + i];
        s.x += t.x; s.y += t.y; s.z += t.z; s.w += t.w;
    }
    ((float4*)out)[i] = s;
}

// ------------------------- launch ------------------------------------------
extern "C" void kernel_launch(void* const* d_in, const int* in_sizes, int n_in,
                              void* d_out, int out_size) {
    const float* hidden = 0; const float* w_qkv = 0; const float* w_o = 0;
    const float* k_cache = 0; const float* v_cache = 0;
    const int* positions = 0; const int* btables = 0;
    for (int i = 0; i < n_in; i++) {
        int sz = in_sizes[i];
        if (sz == B_ * HID_)               hidden  = (const float*)d_in[i];
        else if (sz == HID_ * QKV_N)       w_qkv   = (const float*)d_in[i];
        else if (sz == NH_ * HD_ * HID_)   w_o     = (const float*)d_in[i];
        else if (sz == 4096 * BS_ * NKV_ * HD_) {
            if (!k_cache) k_cache = (const float*)d_in[i];
            else if (!v_cache) v_cache = (const float*)d_in[i];
        }
        else if (sz == B_) { if (!positions) positions = (const int*)d_in[i]; }
        else if (sz == B_ * MAXB_)         btables = (const int*)d_in[i];
    }
    float* out = (float*)d_out;

    noop_kernel<<<1, 32>>>();
    noop_kernel<<<1, 32>>>();
    // 1. qkv = hidden @ w_qkv  (3xFP16 m16n8k16, split-K=16)
    prep16_kernel<<<256, 256>>>(hidden);
    gemm_fp16_kernel<<<dim3(QKV_N / GNT, SPLITK), 128>>>(w_qkv, QKV_N);
    // 2. combine + RoPE
    rope_qk_kernel<<<B_ * 10, 128>>>(positions);
    rope_v_kernel<<<B_ * 2, 128>>>();
    // 3. paged attention
    attn_partial_kernel<<<B_ * NKV_ * NCHUNK, 256>>>(k_cache, v_cache, positions, btables);
    attn_combine_kernel<<<B_ * NKV_, 128>>>(positions);
    // 4. out = attn @ w_o
    prep16_attn_kernel<<<256, 256>>>();
    gemm_fp16_kernel<<<dim3(HID_ / GNT, SPLITK), 128>>>(w_o, HID_);
    add_out_kernel<<<B_ * HID_ / 4 / 256, 256>>>(out);
}